// round 13
// baseline (speedup 1.0000x reference)
#include <cuda_runtime.h>
#include <cuda_bf16.h>
#include <cuda_fp16.h>
#include <cstdint>

// ---------------- problem constants ----------------
#define S       2048
#define DIM     4096
#define NH      32
#define HD      128
#define QKV_N   6144
#define K_OFF   4096
#define V_OFF   5120

// ---------------- scratch (device globals) ----------------
__device__ __half g_qh[S * QKV_N], g_ql[S * QKV_N];   // rope'd qkv, fp16 hi/lo
__device__ __half g_xh[S * DIM];                      // x fp16 hi
__device__ __half g_wh[QKV_N * DIM];                  // packed wq|wk|wv fp16 hi
__device__ __half g_oh[DIM * DIM];                    // wo fp16 hi
__device__ __half g_ah[S * DIM];                      // attention out fp16 hi

// ---------------- helpers ----------------
__device__ __forceinline__ uint32_t smem_u32(const void* p) {
    uint32_t a;
    asm("{ .reg .u64 t; cvta.to.shared.u64 t, %1; cvt.u32.u64 %0, t; }" : "=r"(a) : "l"(p));
    return a;
}
__device__ __forceinline__ void cp16(uint32_t dst, const void* src) {
    asm volatile("cp.async.cg.shared.global [%0], [%1], 16;" :: "r"(dst), "l"(src));
}
__device__ __forceinline__ void cp_commit() {
    asm volatile("cp.async.commit_group;");
}
template <int N>
__device__ __forceinline__ void cp_wait() {
    asm volatile("cp.async.wait_group %0;" :: "n"(N));
}
__device__ __forceinline__ void ldm_x4(uint32_t* r, uint32_t addr) {
    asm volatile("ldmatrix.sync.aligned.m8n8.x4.shared.b16 {%0,%1,%2,%3}, [%4];"
                 : "=r"(r[0]), "=r"(r[1]), "=r"(r[2]), "=r"(r[3]) : "r"(addr));
}
__device__ __forceinline__ void ldm_x4t(uint32_t* r, uint32_t addr) {
    asm volatile("ldmatrix.sync.aligned.m8n8.x4.trans.shared.b16 {%0,%1,%2,%3}, [%4];"
                 : "=r"(r[0]), "=r"(r[1]), "=r"(r[2]), "=r"(r[3]) : "r"(addr));
}
__device__ __forceinline__ void mma_f16(float* c, const uint32_t* a, uint32_t b0, uint32_t b1) {
    asm volatile(
        "mma.sync.aligned.m16n8k16.row.col.f32.f16.f16.f32 "
        "{%0,%1,%2,%3}, {%4,%5,%6,%7}, {%8,%9}, {%0,%1,%2,%3};"
        : "+f"(c[0]), "+f"(c[1]), "+f"(c[2]), "+f"(c[3])
        : "r"(a[0]), "r"(a[1]), "r"(a[2]), "r"(a[3]), "r"(b0), "r"(b1));
}
__device__ __forceinline__ void pack_hl_f16(float x, float y, uint32_t& h, uint32_t& l) {
    __half2 hb = __floats2half2_rn(x, y);
    float hx = __low2float(hb), hy = __high2float(hb);
    __half2 lb = __floats2half2_rn(x - hx, y - hy);
    h = *reinterpret_cast<uint32_t*>(&hb);
    l = *reinterpret_cast<uint32_t*>(&lb);
}
__device__ __forceinline__ uint32_t pack_f16(float x, float y) {
    __half2 hb = __floats2half2_rn(x, y);
    return *reinterpret_cast<uint32_t*>(&hb);
}

// ---------------- splits ----------------
__global__ void split_f16h(const float* __restrict__ src, __half* __restrict__ hi, int n4)
{
    int i = blockIdx.x * blockDim.x + threadIdx.x;
    if (i >= n4) return;
    float4 v = ((const float4*)src)[i];
    ((__half2*)hi)[2 * i]     = __floats2half2_rn(v.x, v.y);
    ((__half2*)hi)[2 * i + 1] = __floats2half2_rn(v.z, v.w);
}

#define NQ4 (DIM * DIM / 4)
#define NK4 (1024 * DIM / 4)
__global__ void split_weights(const float* __restrict__ wq, const float* __restrict__ wk,
                              const float* __restrict__ wv, const float* __restrict__ wo,
                              __half* __restrict__ wh, __half* __restrict__ oh)
{
    int i = blockIdx.x * blockDim.x + threadIdx.x;
    if (i >= 2 * NQ4 + 2 * NK4) return;
    const float* src;
    __half* dst;
    int j;
    if (i < NQ4)                 { j = i;                src = wq; dst = wh; }
    else if (i < NQ4 + NK4)      { j = i - NQ4;          src = wk; dst = wh + (size_t)4096 * DIM; }
    else if (i < NQ4 + 2 * NK4)  { j = i - NQ4 - NK4;    src = wv; dst = wh + (size_t)5120 * DIM; }
    else                         { j = i - NQ4 - 2*NK4;  src = wo; dst = oh; }
    float4 v = ((const float4*)src)[j];
    ((__half2*)dst)[2 * j]     = __floats2half2_rn(v.x, v.y);
    ((__half2*)dst)[2 * j + 1] = __floats2half2_rn(v.z, v.w);
}

// ---------------- fp16 1-term GEMM, CTA 128x128, warp 32x64, 3-stage, 2 CTAs/SM ----
#define GA_HI 0
#define GB_HI (16 * 1024)
#define GSTG  (32 * 1024)
#define GEMM_SMEM (3 * GSTG)

__global__ __launch_bounds__(256, 2) void gemm_f16(
    const __half* __restrict__ Ah, const __half* __restrict__ Bh,
    float* __restrict__ C, int K, int ldc, int mode,
    const float* __restrict__ cs, const float* __restrict__ sn,
    __half* __restrict__ Oh, __half* __restrict__ Ol)
{
    extern __shared__ __align__(1024) char smc[];
    const uint32_t sbase = smem_u32(smc);

    const int tid  = threadIdx.x;
    const int lane = tid & 31;
    const int wid  = tid >> 5;
    const int wm   = wid & 3;
    const int wn   = wid >> 2;
    const int m0 = blockIdx.x * 128;
    const int n0 = blockIdx.y * 128;

    const int grp = lane >> 3;
    const int rin = lane & 7;

    float acc[2][8][4];
    #pragma unroll
    for (int i = 0; i < 2; i++)
        #pragma unroll
        for (int j = 0; j < 8; j++)
            #pragma unroll
            for (int q = 0; q < 4; q++) acc[i][j][q] = 0.f;

    const int nk = K >> 6;

    auto load_chunk = [&](int it) {
        const int k0 = it << 6;
        const uint32_t sb = sbase + (uint32_t)(it % 3) * GSTG;
        #pragma unroll
        for (int i = 0; i < 4; i++) {
            int id = tid + i * 256;
            int row = id >> 3, c16 = id & 7;
            uint32_t so = (uint32_t)(row * 128) + ((uint32_t)(c16 ^ (row & 7)) << 4);
            size_t g = (size_t)(m0 + row) * K + k0 + c16 * 8;
            cp16(sb + GA_HI + so, Ah + g);
        }
        #pragma unroll
        for (int i = 0; i < 4; i++) {
            int id = tid + i * 256;
            int row = id >> 3, c16 = id & 7;
            uint32_t so = (uint32_t)(row * 128) + ((uint32_t)(c16 ^ (row & 7)) << 4);
            size_t g = (size_t)(n0 + row) * K + k0 + c16 * 8;
            cp16(sb + GB_HI + so, Bh + g);
        }
        cp_commit();
    };

    load_chunk(0);
    if (nk > 1) load_chunk(1); else cp_commit();

    for (int it = 0; it < nk; it++) {
        if (it + 2 < nk) load_chunk(it + 2); else cp_commit();
        cp_wait<2>();
        __syncthreads();

        const uint32_t sA = sbase + (uint32_t)(it % 3) * GSTG;
        const uint32_t sB = sA + GB_HI;
        #pragma unroll
        for (int kc = 0; kc < 4; kc++) {
            const int c16 = kc * 2 + (grp >> 1);

            uint32_t ah[2][4];
            #pragma unroll
            for (int am = 0; am < 2; am++) {
                int row = wm * 32 + am * 16 + rin + (grp & 1) * 8;
                uint32_t so = (uint32_t)(row * 128) + ((uint32_t)(c16 ^ (row & 7)) << 4);
                ldm_x4(ah[am], sA + so);
            }
            #pragma unroll
            for (int bt = 0; bt < 4; bt++) {
                int row = wn * 64 + bt * 16 + rin + (grp & 1) * 8;
                uint32_t so = (uint32_t)(row * 128) + ((uint32_t)(c16 ^ (row & 7)) << 4);
                uint32_t bh[4];
                ldm_x4(bh, sB + so);
                #pragma unroll
                for (int am = 0; am < 2; am++) {
                    mma_f16(acc[am][2 * bt],     ah[am], bh[0], bh[2]);
                    mma_f16(acc[am][2 * bt + 1], ah[am], bh[1], bh[3]);
                }
            }
        }
        __syncthreads();
    }

    if (mode == 0) {
        #pragma unroll
        for (int am = 0; am < 2; am++) {
            int row = m0 + wm * 32 + am * 16 + (lane >> 2);
            #pragma unroll
            for (int bn = 0; bn < 8; bn++) {
                int col = n0 + wn * 64 + bn * 8 + (lane & 3) * 2;
                *(float2*)&C[(size_t)row * ldc + col]       = make_float2(acc[am][bn][0], acc[am][bn][1]);
                *(float2*)&C[(size_t)(row + 8) * ldc + col] = make_float2(acc[am][bn][2], acc[am][bn][3]);
            }
        }
    } else {
        #pragma unroll
        for (int am = 0; am < 2; am++) {
            int row = m0 + wm * 32 + am * 16 + (lane >> 2);
            #pragma unroll
            for (int bn = 0; bn < 8; bn++) {
                int col = n0 + wn * 64 + bn * 8 + (lane & 3) * 2;
                int i = (col & (HD - 1)) >> 1;
                bool rope = col < V_OFF;
                #pragma unroll
                for (int half = 0; half < 2; half++) {
                    int r = row + half * 8;
                    float v0 = acc[am][bn][2 * half], v1 = acc[am][bn][2 * half + 1];
                    if (rope) {
                        float c = cs[r * 64 + i], si = sn[r * 64 + i];
                        float t0 = v0 * c - v1 * si;
                        float t1 = v0 * si + v1 * c;
                        v0 = t0; v1 = t1;
                    }
                    uint32_t hb, lb;
                    pack_hl_f16(v0, v1, hb, lb);
                    *(uint32_t*)&Oh[(size_t)r * ldc + col] = hb;
                    *(uint32_t*)&Ol[(size_t)r * ldc + col] = lb;
                }
            }
        }
    }
}

// ---------------- tensor-core flash attention (fp16, causal, GQA 4:1) ----------------
// CTA: 128 threads (4 warps), q-tile 64, 2 CTAs/SM.
// QK^T: (Qh + Ql) * Kh ; PV: P * Vh
// Smem: Qh 16K | Ql 16K | 2 KV stages x (Kh 16K + Vh 16K) = 96KB
#define ATT_SMEM (96 * 1024)

__global__ __launch_bounds__(128, 2) void attn_mma(
    const __half* __restrict__ qh_g, const __half* __restrict__ ql_g,
    __half* __restrict__ ah_g)
{
    extern __shared__ __align__(1024) char smb[];
    const uint32_t sb = smem_u32(smb);
    const uint32_t sQh = sb, sQl = sb + 16 * 1024;

    const int tid = threadIdx.x, lane = tid & 31, wid = tid >> 5;
    const int qt = (int)gridDim.x - 1 - (int)blockIdx.x;
    const int h = blockIdx.y, kvh = h >> 2;
    const int q0 = qt * 64;
    const int wq = wid * 16;

    // Q tile load: 64 rows x 128 cols fp16 (hi+lo), 1024 16B-lines each
    #pragma unroll
    for (int i = 0; i < 8; i++) {
        int ch = tid + i * 128;
        int row = ch >> 4, c16 = ch & 15;
        uint32_t so = (uint32_t)(row * 256) + (uint32_t)((c16 ^ (row & 7)) << 4);
        size_t g = (size_t)(q0 + row) * QKV_N + h * HD + c16 * 8;
        cp16(sQh + so, qh_g + g);
        cp16(sQl + so, ql_g + g);
    }
    cp_commit();

    const int ktmax = qt;
    auto load_kv = [&](int kt) {
        const uint32_t st = sb + 32 * 1024 + (uint32_t)(kt & 1) * 32 * 1024;
        const int k0 = kt * 64;
        #pragma unroll
        for (int i = 0; i < 8; i++) {
            int ch = tid + i * 128;
            int row = ch >> 4, c16 = ch & 15;
            uint32_t so = (uint32_t)(row * 256) + (uint32_t)((c16 ^ (row & 7)) << 4);
            size_t kb = (size_t)(k0 + row) * QKV_N + kvh * HD + c16 * 8;
            cp16(st + so,             qh_g + kb + K_OFF);
            cp16(st + 16 * 1024 + so, qh_g + kb + V_OFF);
        }
        cp_commit();
    };
    load_kv(0);

    float oacc[16][4];
    #pragma unroll
    for (int a = 0; a < 16; a++)
        #pragma unroll
        for (int q = 0; q < 4; q++) oacc[a][q] = 0.f;
    float m0 = -1e30f, m1 = -1e30f, l0 = 0.f, l1 = 0.f;
    const float kscale = 0.08838834764831845f * 1.44269504088896f;

    const int rin = lane & 7, grp = lane >> 3;
    const int arow = wq + rin + (grp & 1) * 8;
    const int r0 = lane >> 2;

    for (int kt = 0; kt <= ktmax; kt++) {
        if (kt < ktmax) { load_kv(kt + 1); cp_wait<1>(); }
        else            { cp_wait<0>(); }
        __syncthreads();

        {
            const uint32_t st = sb + 32 * 1024 + (uint32_t)(kt & 1) * 32 * 1024;

            float sc[8][4];
            #pragma unroll
            for (int a = 0; a < 8; a++)
                #pragma unroll
                for (int q = 0; q < 4; q++) sc[a][q] = 0.f;

            // QK^T: (Qh + Ql) * Kh
            #pragma unroll
            for (int k16 = 0; k16 < 8; k16++) {
                const int c16 = k16 * 2 + (grp >> 1);
                uint32_t aoff = (uint32_t)(arow * 256) + (uint32_t)((c16 ^ (arow & 7)) << 4);
                uint32_t aqh[4], aql[4];
                ldm_x4(aqh, sQh + aoff);
                ldm_x4(aql, sQl + aoff);
                #pragma unroll
                for (int bp = 0; bp < 2; bp++) {
                    uint32_t bh[2][4];
                    #pragma unroll
                    for (int t = 0; t < 2; t++) {
                        int brow = (bp * 2 + t) * 16 + rin + (grp & 1) * 8;
                        uint32_t boff = (uint32_t)(brow * 256) + (uint32_t)((c16 ^ (brow & 7)) << 4);
                        ldm_x4(bh[t], st + boff);
                    }
                    #pragma unroll
                    for (int t = 0; t < 2; t++) {
                        int b = bp * 2 + t;
                        mma_f16(sc[2 * b],     aqh, bh[t][0], bh[t][2]);
                        mma_f16(sc[2 * b + 1], aqh, bh[t][1], bh[t][3]);
                    }
                    #pragma unroll
                    for (int t = 0; t < 2; t++) {
                        int b = bp * 2 + t;
                        mma_f16(sc[2 * b],     aql, bh[t][0], bh[t][2]);
                        mma_f16(sc[2 * b + 1], aql, bh[t][1], bh[t][3]);
                    }
                }
            }

            if (kt * 64 + 63 > q0 + wq) {
                int qr0 = q0 + wq + r0, qr1 = qr0 + 8;
                int cb = kt * 64 + 2 * (lane & 3);
                #pragma unroll
                for (int a = 0; a < 8; a++) {
                    int c0 = cb + a * 8, c1 = c0 + 1;
                    if (c0 > qr0) sc[a][0] = -1e30f;
                    if (c1 > qr0) sc[a][1] = -1e30f;
                    if (c0 > qr1) sc[a][2] = -1e30f;
                    if (c1 > qr1) sc[a][3] = -1e30f;
                }
            }

            float mx0 = -1e30f, mx1 = -1e30f;
            #pragma unroll
            for (int a = 0; a < 8; a++) {
                mx0 = fmaxf(mx0, fmaxf(sc[a][0], sc[a][1]));
                mx1 = fmaxf(mx1, fmaxf(sc[a][2], sc[a][3]));
            }
            mx0 = fmaxf(mx0, __shfl_xor_sync(0xffffffffu, mx0, 1));
            mx0 = fmaxf(mx0, __shfl_xor_sync(0xffffffffu, mx0, 2));
            mx1 = fmaxf(mx1, __shfl_xor_sync(0xffffffffu, mx1, 1));
            mx1 = fmaxf(mx1, __shfl_xor_sync(0xffffffffu, mx1, 2));
            float nm0 = fmaxf(m0, mx0), nm1 = fmaxf(m1, mx1);
            float corr0 = exp2f((m0 - nm0) * kscale);
            float corr1 = exp2f((m1 - nm1) * kscale);
            float s0 = 0.f, s1 = 0.f;
            #pragma unroll
            for (int a = 0; a < 8; a++) {
                sc[a][0] = exp2f((sc[a][0] - nm0) * kscale);
                sc[a][1] = exp2f((sc[a][1] - nm0) * kscale);
                sc[a][2] = exp2f((sc[a][2] - nm1) * kscale);
                sc[a][3] = exp2f((sc[a][3] - nm1) * kscale);
                s0 += sc[a][0] + sc[a][1];
                s1 += sc[a][2] + sc[a][3];
            }
            s0 += __shfl_xor_sync(0xffffffffu, s0, 1);
            s0 += __shfl_xor_sync(0xffffffffu, s0, 2);
            s1 += __shfl_xor_sync(0xffffffffu, s1, 1);
            s1 += __shfl_xor_sync(0xffffffffu, s1, 2);
            l0 = l0 * corr0 + s0;
            l1 = l1 * corr1 + s1;
            m0 = nm0; m1 = nm1;
            #pragma unroll
            for (int a = 0; a < 16; a++) {
                oacc[a][0] *= corr0; oacc[a][1] *= corr0;
                oacc[a][2] *= corr1; oacc[a][3] *= corr1;
            }

            // PV: P * Vh
            #pragma unroll
            for (int t = 0; t < 4; t++) {
                uint32_t ph[4];
                ph[0] = pack_f16(sc[2 * t][0],     sc[2 * t][1]);
                ph[1] = pack_f16(sc[2 * t][2],     sc[2 * t][3]);
                ph[2] = pack_f16(sc[2 * t + 1][0], sc[2 * t + 1][1]);
                ph[3] = pack_f16(sc[2 * t + 1][2], sc[2 * t + 1][3]);
                #pragma unroll
                for (int dp = 0; dp < 4; dp++) {
                    uint32_t vh[2][4];
                    #pragma unroll
                    for (int u = 0; u < 2; u++) {
                        int d = dp * 2 + u;
                        int vrow = t * 16 + (grp & 1) * 8 + rin;
                        int c16 = d * 2 + (grp >> 1);
                        uint32_t voff = (uint32_t)(vrow * 256) + (uint32_t)((c16 ^ (vrow & 7)) << 4);
                        ldm_x4t(vh[u], st + 16 * 1024 + voff);
                    }
                    #pragma unroll
                    for (int u = 0; u < 2; u++) {
                        int d = dp * 2 + u;
                        mma_f16(oacc[2 * d],     ph, vh[u][0], vh[u][1]);
                        mma_f16(oacc[2 * d + 1], ph, vh[u][2], vh[u][3]);
                    }
                }
            }
        }
        __syncthreads();
    }

    float inv0 = 1.f / l0, inv1 = 1.f / l1;
    int gr0 = q0 + wq + r0, gr1 = gr0 + 8;
    #pragma unroll
    for (int a = 0; a < 16; a++) {
        int d0 = a * 8 + 2 * (lane & 3);
        *(uint32_t*)&ah_g[(size_t)gr0 * DIM + h * HD + d0] =
            pack_f16(oacc[a][0] * inv0, oacc[a][1] * inv0);
        *(uint32_t*)&ah_g[(size_t)gr1 * DIM + h * HD + d0] =
            pack_f16(oacc[a][2] * inv1, oacc[a][3] * inv1);
    }
}

// ---------------- launch ----------------
extern "C" void kernel_launch(void* const* d_in, const int* in_sizes, int n_in,
                              void* d_out, int out_size)
{
    const float* x  = (const float*)d_in[0];
    const float* fc = (const float*)d_in[1];
    const float* fs = (const float*)d_in[2];
    const float* wq = (const float*)d_in[5];
    const float* wk = (const float*)d_in[6];
    const float* wv = (const float*)d_in[7];
    const float* wo = (const float*)d_in[8];
    float* out = (float*)d_out;

    __half *qh, *ql, *xh, *wh, *oh, *ah;
    cudaGetSymbolAddress((void**)&qh, g_qh);  cudaGetSymbolAddress((void**)&ql, g_ql);
    cudaGetSymbolAddress((void**)&xh, g_xh);
    cudaGetSymbolAddress((void**)&wh, g_wh);  cudaGetSymbolAddress((void**)&oh, g_oh);
    cudaGetSymbolAddress((void**)&ah, g_ah);

    cudaFuncSetAttribute(gemm_f16, cudaFuncAttributeMaxDynamicSharedMemorySize, GEMM_SMEM);
    cudaFuncSetAttribute(attn_mma, cudaFuncAttributeMaxDynamicSharedMemorySize, ATT_SMEM);

    dim3 blk(256);
    int n4x = S * DIM / 4;
    split_f16h<<<(n4x + 255) / 256, blk>>>(x, xh, n4x);
    int n4w = 2 * NQ4 + 2 * NK4;
    split_weights<<<(n4w + 255) / 256, blk>>>(wq, wk, wv, wo, wh, oh);

    // QKV projection (fp16 1-term) with fused RoPE + fp16 hi/lo split epilogue
    gemm_f16<<<dim3(S / 128, QKV_N / 128), blk, GEMM_SMEM>>>(
        xh, wh, nullptr, DIM, QKV_N, 1, fc, fs, qh, ql);

    // tensor-core attention (fp16), 4-warp CTAs, 2 CTAs/SM
    attn_mma<<<dim3(S / 64, NH), dim3(128), ATT_SMEM>>>(qh, ql, ah);

    // output projection (fp16 1-term) -> fp32 out
    gemm_f16<<<dim3(S / 128, DIM / 128), blk, GEMM_SMEM>>>(
        ah, oh, out, DIM, DIM, 0, nullptr, nullptr, nullptr, nullptr);
}

// round 14
// speedup vs baseline: 1.4909x; 1.4909x over previous
#include <cuda_runtime.h>
#include <cuda_bf16.h>
#include <cuda_fp16.h>
#include <cstdint>

// ---------------- problem constants ----------------
#define S       2048
#define DIM     4096
#define NH      32
#define HD      128
#define QKV_N   6144
#define K_OFF   4096
#define V_OFF   5120

// ---------------- scratch (device globals) ----------------
__device__ __half g_qh[S * QKV_N], g_ql[S * QKV_N];   // rope'd qkv, fp16 hi/lo
__device__ __half g_xh[S * DIM];                      // x fp16 hi
__device__ __half g_wh[QKV_N * DIM];                  // packed wq|wk|wv fp16 hi
__device__ __half g_oh[DIM * DIM];                    // wo fp16 hi
__device__ __half g_ah[S * DIM];                      // attention out fp16 hi

// ---------------- helpers ----------------
__device__ __forceinline__ uint32_t smem_u32(const void* p) {
    uint32_t a;
    asm("{ .reg .u64 t; cvta.to.shared.u64 t, %1; cvt.u32.u64 %0, t; }" : "=r"(a) : "l"(p));
    return a;
}
__device__ __forceinline__ void cp16(uint32_t dst, const void* src) {
    asm volatile("cp.async.cg.shared.global [%0], [%1], 16;" :: "r"(dst), "l"(src));
}
__device__ __forceinline__ void cp_commit() {
    asm volatile("cp.async.commit_group;");
}
template <int N>
__device__ __forceinline__ void cp_wait() {
    asm volatile("cp.async.wait_group %0;" :: "n"(N));
}
__device__ __forceinline__ void ldm_x4(uint32_t* r, uint32_t addr) {
    asm volatile("ldmatrix.sync.aligned.m8n8.x4.shared.b16 {%0,%1,%2,%3}, [%4];"
                 : "=r"(r[0]), "=r"(r[1]), "=r"(r[2]), "=r"(r[3]) : "r"(addr));
}
__device__ __forceinline__ void ldm_x4t(uint32_t* r, uint32_t addr) {
    asm volatile("ldmatrix.sync.aligned.m8n8.x4.trans.shared.b16 {%0,%1,%2,%3}, [%4];"
                 : "=r"(r[0]), "=r"(r[1]), "=r"(r[2]), "=r"(r[3]) : "r"(addr));
}
__device__ __forceinline__ void mma_f16(float* c, const uint32_t* a, uint32_t b0, uint32_t b1) {
    asm volatile(
        "mma.sync.aligned.m16n8k16.row.col.f32.f16.f16.f32 "
        "{%0,%1,%2,%3}, {%4,%5,%6,%7}, {%8,%9}, {%0,%1,%2,%3};"
        : "+f"(c[0]), "+f"(c[1]), "+f"(c[2]), "+f"(c[3])
        : "r"(a[0]), "r"(a[1]), "r"(a[2]), "r"(a[3]), "r"(b0), "r"(b1));
}
__device__ __forceinline__ void pack_hl_f16(float x, float y, uint32_t& h, uint32_t& l) {
    __half2 hb = __floats2half2_rn(x, y);
    float hx = __low2float(hb), hy = __high2float(hb);
    __half2 lb = __floats2half2_rn(x - hx, y - hy);
    h = *reinterpret_cast<uint32_t*>(&hb);
    l = *reinterpret_cast<uint32_t*>(&lb);
}
__device__ __forceinline__ uint32_t pack_f16(float x, float y) {
    __half2 hb = __floats2half2_rn(x, y);
    return *reinterpret_cast<uint32_t*>(&hb);
}

// ---------------- one fused split: x | wq | wk | wv | wo -> fp16 hi ----------------
#define NX4 (S * DIM / 4)
#define NQ4 (DIM * DIM / 4)
#define NK4 (1024 * DIM / 4)
#define NTOT4 (NX4 + 2 * NQ4 + 2 * NK4)
__global__ void split_all(const float* __restrict__ x,
                          const float* __restrict__ wq, const float* __restrict__ wk,
                          const float* __restrict__ wv, const float* __restrict__ wo,
                          __half* __restrict__ xh, __half* __restrict__ wh,
                          __half* __restrict__ oh)
{
    int i = blockIdx.x * blockDim.x + threadIdx.x;
    if (i >= NTOT4) return;
    const float* src;
    __half* dst;
    int j;
    if (i < NX4)                           { j = i;                       src = x;  dst = xh; }
    else if (i < NX4 + NQ4)                { j = i - NX4;                 src = wq; dst = wh; }
    else if (i < NX4 + NQ4 + NK4)          { j = i - NX4 - NQ4;           src = wk; dst = wh + (size_t)4096 * DIM; }
    else if (i < NX4 + NQ4 + 2 * NK4)      { j = i - NX4 - NQ4 - NK4;     src = wv; dst = wh + (size_t)5120 * DIM; }
    else                                   { j = i - NX4 - NQ4 - 2 * NK4; src = wo; dst = oh; }
    float4 v = ((const float4*)src)[j];
    ((__half2*)dst)[2 * j]     = __floats2half2_rn(v.x, v.y);
    ((__half2*)dst)[2 * j + 1] = __floats2half2_rn(v.z, v.w);
}

// ---------------- fp16 1-term GEMM, CTA 128x128, warp 32x64, 3-stage, 2 CTAs/SM ----
#define GA_HI 0
#define GB_HI (16 * 1024)
#define GSTG  (32 * 1024)
#define GEMM_SMEM (3 * GSTG)

__global__ __launch_bounds__(256, 2) void gemm_f16(
    const __half* __restrict__ Ah, const __half* __restrict__ Bh,
    float* __restrict__ C, int K, int ldc, int mode,
    const float* __restrict__ cs, const float* __restrict__ sn,
    __half* __restrict__ Oh, __half* __restrict__ Ol)
{
    extern __shared__ __align__(1024) char smc[];
    const uint32_t sbase = smem_u32(smc);

    const int tid  = threadIdx.x;
    const int lane = tid & 31;
    const int wid  = tid >> 5;
    const int wm   = wid & 3;
    const int wn   = wid >> 2;
    const int m0 = blockIdx.x * 128;
    const int n0 = blockIdx.y * 128;

    const int grp = lane >> 3;
    const int rin = lane & 7;

    float acc[2][8][4];
    #pragma unroll
    for (int i = 0; i < 2; i++)
        #pragma unroll
        for (int j = 0; j < 8; j++)
            #pragma unroll
            for (int q = 0; q < 4; q++) acc[i][j][q] = 0.f;

    const int nk = K >> 6;

    auto load_chunk = [&](int it) {
        const int k0 = it << 6;
        const uint32_t sb = sbase + (uint32_t)(it % 3) * GSTG;
        #pragma unroll
        for (int i = 0; i < 4; i++) {
            int id = tid + i * 256;
            int row = id >> 3, c16 = id & 7;
            uint32_t so = (uint32_t)(row * 128) + ((uint32_t)(c16 ^ (row & 7)) << 4);
            size_t g = (size_t)(m0 + row) * K + k0 + c16 * 8;
            cp16(sb + GA_HI + so, Ah + g);
        }
        #pragma unroll
        for (int i = 0; i < 4; i++) {
            int id = tid + i * 256;
            int row = id >> 3, c16 = id & 7;
            uint32_t so = (uint32_t)(row * 128) + ((uint32_t)(c16 ^ (row & 7)) << 4);
            size_t g = (size_t)(n0 + row) * K + k0 + c16 * 8;
            cp16(sb + GB_HI + so, Bh + g);
        }
        cp_commit();
    };

    load_chunk(0);
    if (nk > 1) load_chunk(1); else cp_commit();

    for (int it = 0; it < nk; it++) {
        if (it + 2 < nk) load_chunk(it + 2); else cp_commit();
        cp_wait<2>();
        __syncthreads();

        const uint32_t sA = sbase + (uint32_t)(it % 3) * GSTG;
        const uint32_t sB = sA + GB_HI;
        #pragma unroll
        for (int kc = 0; kc < 4; kc++) {
            const int c16 = kc * 2 + (grp >> 1);

            uint32_t ah[2][4];
            #pragma unroll
            for (int am = 0; am < 2; am++) {
                int row = wm * 32 + am * 16 + rin + (grp & 1) * 8;
                uint32_t so = (uint32_t)(row * 128) + ((uint32_t)(c16 ^ (row & 7)) << 4);
                ldm_x4(ah[am], sA + so);
            }
            #pragma unroll
            for (int bt = 0; bt < 4; bt++) {
                int row = wn * 64 + bt * 16 + rin + (grp & 1) * 8;
                uint32_t so = (uint32_t)(row * 128) + ((uint32_t)(c16 ^ (row & 7)) << 4);
                uint32_t bh[4];
                ldm_x4(bh, sB + so);
                #pragma unroll
                for (int am = 0; am < 2; am++) {
                    mma_f16(acc[am][2 * bt],     ah[am], bh[0], bh[2]);
                    mma_f16(acc[am][2 * bt + 1], ah[am], bh[1], bh[3]);
                }
            }
        }
        __syncthreads();
    }

    if (mode == 0) {
        #pragma unroll
        for (int am = 0; am < 2; am++) {
            int row = m0 + wm * 32 + am * 16 + (lane >> 2);
            #pragma unroll
            for (int bn = 0; bn < 8; bn++) {
                int col = n0 + wn * 64 + bn * 8 + (lane & 3) * 2;
                *(float2*)&C[(size_t)row * ldc + col]       = make_float2(acc[am][bn][0], acc[am][bn][1]);
                *(float2*)&C[(size_t)(row + 8) * ldc + col] = make_float2(acc[am][bn][2], acc[am][bn][3]);
            }
        }
    } else {
        #pragma unroll
        for (int am = 0; am < 2; am++) {
            int row = m0 + wm * 32 + am * 16 + (lane >> 2);
            #pragma unroll
            for (int bn = 0; bn < 8; bn++) {
                int col = n0 + wn * 64 + bn * 8 + (lane & 3) * 2;
                int i = (col & (HD - 1)) >> 1;
                bool rope = col < V_OFF;
                #pragma unroll
                for (int half = 0; half < 2; half++) {
                    int r = row + half * 8;
                    float v0 = acc[am][bn][2 * half], v1 = acc[am][bn][2 * half + 1];
                    if (rope) {
                        float c = cs[r * 64 + i], si = sn[r * 64 + i];
                        float t0 = v0 * c - v1 * si;
                        float t1 = v0 * si + v1 * c;
                        v0 = t0; v1 = t1;
                    }
                    uint32_t hb, lb;
                    pack_hl_f16(v0, v1, hb, lb);
                    *(uint32_t*)&Oh[(size_t)r * ldc + col] = hb;
                    *(uint32_t*)&Ol[(size_t)r * ldc + col] = lb;
                }
            }
        }
    }
}

// ---------------- tensor-core flash attention (fp16, causal, GQA 4:1) ----------------
// R12 shape: CTA 256 threads, q-tile 128, 1 CTA/SM.
// QK^T: (Qh + Ql) * Kh ; PV: P * Vh
#define ATT_SMEM (128 * 1024)

__global__ __launch_bounds__(256, 1) void attn_mma(
    const __half* __restrict__ qh_g, const __half* __restrict__ ql_g,
    __half* __restrict__ ah_g)
{
    extern __shared__ __align__(1024) char smb[];
    const uint32_t sb = smem_u32(smb);
    const uint32_t sQh = sb, sQl = sb + 32 * 1024;

    const int tid = threadIdx.x, lane = tid & 31, wid = tid >> 5;
    const int qt = (int)gridDim.x - 1 - (int)blockIdx.x;
    const int h = blockIdx.y, kvh = h >> 2;
    const int q0 = qt * 128;
    const int wq = wid * 16;

    #pragma unroll
    for (int i = 0; i < 8; i++) {
        int ch = tid + i * 256;
        int row = ch >> 4, c16 = ch & 15;
        uint32_t so = (uint32_t)(row * 256) + (uint32_t)((c16 ^ (row & 7)) << 4);
        size_t g = (size_t)(q0 + row) * QKV_N + h * HD + c16 * 8;
        cp16(sQh + so, qh_g + g);
        cp16(sQl + so, ql_g + g);
    }
    cp_commit();

    const int ktmax = 2 * qt + 1;
    auto load_kv = [&](int kt) {
        const uint32_t st = sb + 64 * 1024 + (uint32_t)(kt & 1) * 32 * 1024;
        const int k0 = kt * 64;
        #pragma unroll
        for (int i = 0; i < 4; i++) {
            int ch = tid + i * 256;
            int row = ch >> 4, c16 = ch & 15;
            uint32_t so = (uint32_t)(row * 256) + (uint32_t)((c16 ^ (row & 7)) << 4);
            size_t kb = (size_t)(k0 + row) * QKV_N + kvh * HD + c16 * 8;
            cp16(st + so,             qh_g + kb + K_OFF);
            cp16(st + 16 * 1024 + so, qh_g + kb + V_OFF);
        }
        cp_commit();
    };
    load_kv(0);

    float oacc[16][4];
    #pragma unroll
    for (int a = 0; a < 16; a++)
        #pragma unroll
        for (int q = 0; q < 4; q++) oacc[a][q] = 0.f;
    float m0 = -1e30f, m1 = -1e30f, l0 = 0.f, l1 = 0.f;
    const float kscale = 0.08838834764831845f * 1.44269504088896f;

    const int rin = lane & 7, grp = lane >> 3;
    const int arow = wq + rin + (grp & 1) * 8;
    const int r0 = lane >> 2;

    for (int kt = 0; kt <= ktmax; kt++) {
        if (kt < ktmax) { load_kv(kt + 1); cp_wait<1>(); }
        else            { cp_wait<0>(); }
        __syncthreads();

        const bool skip = (kt * 64) > (q0 + wq + 15);
        if (!skip) {
            const uint32_t st = sb + 64 * 1024 + (uint32_t)(kt & 1) * 32 * 1024;

            float sc[8][4];
            #pragma unroll
            for (int a = 0; a < 8; a++)
                #pragma unroll
                for (int q = 0; q < 4; q++) sc[a][q] = 0.f;

            #pragma unroll
            for (int k16 = 0; k16 < 8; k16++) {
                const int c16 = k16 * 2 + (grp >> 1);
                uint32_t aoff = (uint32_t)(arow * 256) + (uint32_t)((c16 ^ (arow & 7)) << 4);
                uint32_t aqh[4], aql[4];
                ldm_x4(aqh, sQh + aoff);
                ldm_x4(aql, sQl + aoff);
                #pragma unroll
                for (int bp = 0; bp < 2; bp++) {
                    uint32_t bh[2][4];
                    #pragma unroll
                    for (int t = 0; t < 2; t++) {
                        int brow = (bp * 2 + t) * 16 + rin + (grp & 1) * 8;
                        uint32_t boff = (uint32_t)(brow * 256) + (uint32_t)((c16 ^ (brow & 7)) << 4);
                        ldm_x4(bh[t], st + boff);
                    }
                    #pragma unroll
                    for (int t = 0; t < 2; t++) {
                        int b = bp * 2 + t;
                        mma_f16(sc[2 * b],     aqh, bh[t][0], bh[t][2]);
                        mma_f16(sc[2 * b + 1], aqh, bh[t][1], bh[t][3]);
                    }
                    #pragma unroll
                    for (int t = 0; t < 2; t++) {
                        int b = bp * 2 + t;
                        mma_f16(sc[2 * b],     aql, bh[t][0], bh[t][2]);
                        mma_f16(sc[2 * b + 1], aql, bh[t][1], bh[t][3]);
                    }
                }
            }

            if (kt * 64 + 63 > q0 + wq) {
                int qr0 = q0 + wq + r0, qr1 = qr0 + 8;
                int cb = kt * 64 + 2 * (lane & 3);
                #pragma unroll
                for (int a = 0; a < 8; a++) {
                    int c0 = cb + a * 8, c1 = c0 + 1;
                    if (c0 > qr0) sc[a][0] = -1e30f;
                    if (c1 > qr0) sc[a][1] = -1e30f;
                    if (c0 > qr1) sc[a][2] = -1e30f;
                    if (c1 > qr1) sc[a][3] = -1e30f;
                }
            }

            float mx0 = -1e30f, mx1 = -1e30f;
            #pragma unroll
            for (int a = 0; a < 8; a++) {
                mx0 = fmaxf(mx0, fmaxf(sc[a][0], sc[a][1]));
                mx1 = fmaxf(mx1, fmaxf(sc[a][2], sc[a][3]));
            }
            mx0 = fmaxf(mx0, __shfl_xor_sync(0xffffffffu, mx0, 1));
            mx0 = fmaxf(mx0, __shfl_xor_sync(0xffffffffu, mx0, 2));
            mx1 = fmaxf(mx1, __shfl_xor_sync(0xffffffffu, mx1, 1));
            mx1 = fmaxf(mx1, __shfl_xor_sync(0xffffffffu, mx1, 2));
            float nm0 = fmaxf(m0, mx0), nm1 = fmaxf(m1, mx1);
            float corr0 = exp2f((m0 - nm0) * kscale);
            float corr1 = exp2f((m1 - nm1) * kscale);
            float s0 = 0.f, s1 = 0.f;
            #pragma unroll
            for (int a = 0; a < 8; a++) {
                sc[a][0] = exp2f((sc[a][0] - nm0) * kscale);
                sc[a][1] = exp2f((sc[a][1] - nm0) * kscale);
                sc[a][2] = exp2f((sc[a][2] - nm1) * kscale);
                sc[a][3] = exp2f((sc[a][3] - nm1) * kscale);
                s0 += sc[a][0] + sc[a][1];
                s1 += sc[a][2] + sc[a][3];
            }
            s0 += __shfl_xor_sync(0xffffffffu, s0, 1);
            s0 += __shfl_xor_sync(0xffffffffu, s0, 2);
            s1 += __shfl_xor_sync(0xffffffffu, s1, 1);
            s1 += __shfl_xor_sync(0xffffffffu, s1, 2);
            l0 = l0 * corr0 + s0;
            l1 = l1 * corr1 + s1;
            m0 = nm0; m1 = nm1;
            #pragma unroll
            for (int a = 0; a < 16; a++) {
                oacc[a][0] *= corr0; oacc[a][1] *= corr0;
                oacc[a][2] *= corr1; oacc[a][3] *= corr1;
            }

            #pragma unroll
            for (int t = 0; t < 4; t++) {
                uint32_t ph[4];
                ph[0] = pack_f16(sc[2 * t][0],     sc[2 * t][1]);
                ph[1] = pack_f16(sc[2 * t][2],     sc[2 * t][3]);
                ph[2] = pack_f16(sc[2 * t + 1][0], sc[2 * t + 1][1]);
                ph[3] = pack_f16(sc[2 * t + 1][2], sc[2 * t + 1][3]);
                #pragma unroll
                for (int dp = 0; dp < 4; dp++) {
                    uint32_t vh[2][4];
                    #pragma unroll
                    for (int u = 0; u < 2; u++) {
                        int d = dp * 2 + u;
                        int vrow = t * 16 + (grp & 1) * 8 + rin;
                        int c16 = d * 2 + (grp >> 1);
                        uint32_t voff = (uint32_t)(vrow * 256) + (uint32_t)((c16 ^ (vrow & 7)) << 4);
                        ldm_x4t(vh[u], st + 16 * 1024 + voff);
                    }
                    #pragma unroll
                    for (int u = 0; u < 2; u++) {
                        int d = dp * 2 + u;
                        mma_f16(oacc[2 * d],     ph, vh[u][0], vh[u][1]);
                        mma_f16(oacc[2 * d + 1], ph, vh[u][2], vh[u][3]);
                    }
                }
            }
        }
        __syncthreads();
    }

    float inv0 = 1.f / l0, inv1 = 1.f / l1;
    int gr0 = q0 + wq + r0, gr1 = gr0 + 8;
    #pragma unroll
    for (int a = 0; a < 16; a++) {
        int d0 = a * 8 + 2 * (lane & 3);
        *(uint32_t*)&ah_g[(size_t)gr0 * DIM + h * HD + d0] =
            pack_f16(oacc[a][0] * inv0, oacc[a][1] * inv0);
        *(uint32_t*)&ah_g[(size_t)gr1 * DIM + h * HD + d0] =
            pack_f16(oacc[a][2] * inv1, oacc[a][3] * inv1);
    }
}

// ---------------- launch ----------------
extern "C" void kernel_launch(void* const* d_in, const int* in_sizes, int n_in,
                              void* d_out, int out_size)
{
    const float* x  = (const float*)d_in[0];
    const float* fc = (const float*)d_in[1];
    const float* fs = (const float*)d_in[2];
    const float* wq = (const float*)d_in[5];
    const float* wk = (const float*)d_in[6];
    const float* wv = (const float*)d_in[7];
    const float* wo = (const float*)d_in[8];
    float* out = (float*)d_out;

    __half *qh, *ql, *xh, *wh, *oh, *ah;
    cudaGetSymbolAddress((void**)&qh, g_qh);  cudaGetSymbolAddress((void**)&ql, g_ql);
    cudaGetSymbolAddress((void**)&xh, g_xh);
    cudaGetSymbolAddress((void**)&wh, g_wh);  cudaGetSymbolAddress((void**)&oh, g_oh);
    cudaGetSymbolAddress((void**)&ah, g_ah);

    cudaFuncSetAttribute(gemm_f16, cudaFuncAttributeMaxDynamicSharedMemorySize, GEMM_SMEM);
    cudaFuncSetAttribute(attn_mma, cudaFuncAttributeMaxDynamicSharedMemorySize, ATT_SMEM);

    dim3 blk(256);
    // one fused split for x + all weights
    split_all<<<(NTOT4 + 255) / 256, blk>>>(x, wq, wk, wv, wo, xh, wh, oh);

    // QKV projection (fp16 1-term) with fused RoPE + fp16 hi/lo split epilogue
    gemm_f16<<<dim3(S / 128, QKV_N / 128), blk, GEMM_SMEM>>>(
        xh, wh, nullptr, DIM, QKV_N, 1, fc, fs, qh, ql);

    // tensor-core attention (fp16), R12 shape
    attn_mma<<<dim3(S / 128, NH), blk, ATT_SMEM>>>(qh, ql, ah);

    // output projection (fp16 1-term) -> fp32 out
    gemm_f16<<<dim3(S / 128, DIM / 128), blk, GEMM_SMEM>>>(
        ah, oh, out, DIM, DIM, 0, nullptr, nullptr, nullptr, nullptr);
}

// round 15
// speedup vs baseline: 1.5306x; 1.0266x over previous
#include <cuda_runtime.h>
#include <cuda_bf16.h>
#include <cuda_fp16.h>
#include <cstdint>

// ---------------- problem constants ----------------
#define S       2048
#define DIM     4096
#define NH      32
#define HD      128
#define QKV_N   6144
#define K_OFF   4096
#define V_OFF   5120

// ---------------- scratch (device globals) ----------------
__device__ __half g_qh[S * QKV_N], g_ql[S * QKV_N];   // rope'd qkv, fp16 hi/lo
__device__ __half g_xh[S * DIM];                      // x fp16 hi
__device__ __half g_wh[QKV_N * DIM];                  // packed wq|wk|wv fp16 hi
__device__ __half g_oh[DIM * DIM];                    // wo fp16 hi
__device__ __half g_ah[S * DIM];                      // attention out fp16 hi

// ---------------- helpers ----------------
__device__ __forceinline__ uint32_t smem_u32(const void* p) {
    uint32_t a;
    asm("{ .reg .u64 t; cvta.to.shared.u64 t, %1; cvt.u32.u64 %0, t; }" : "=r"(a) : "l"(p));
    return a;
}
__device__ __forceinline__ void cp16(uint32_t dst, const void* src) {
    asm volatile("cp.async.cg.shared.global [%0], [%1], 16;" :: "r"(dst), "l"(src));
}
__device__ __forceinline__ void cp_commit() {
    asm volatile("cp.async.commit_group;");
}
template <int N>
__device__ __forceinline__ void cp_wait() {
    asm volatile("cp.async.wait_group %0;" :: "n"(N));
}
__device__ __forceinline__ void ldm_x4(uint32_t* r, uint32_t addr) {
    asm volatile("ldmatrix.sync.aligned.m8n8.x4.shared.b16 {%0,%1,%2,%3}, [%4];"
                 : "=r"(r[0]), "=r"(r[1]), "=r"(r[2]), "=r"(r[3]) : "r"(addr));
}
__device__ __forceinline__ void ldm_x4t(uint32_t* r, uint32_t addr) {
    asm volatile("ldmatrix.sync.aligned.m8n8.x4.trans.shared.b16 {%0,%1,%2,%3}, [%4];"
                 : "=r"(r[0]), "=r"(r[1]), "=r"(r[2]), "=r"(r[3]) : "r"(addr));
}
__device__ __forceinline__ void mma_f16(float* c, const uint32_t* a, uint32_t b0, uint32_t b1) {
    asm volatile(
        "mma.sync.aligned.m16n8k16.row.col.f32.f16.f16.f32 "
        "{%0,%1,%2,%3}, {%4,%5,%6,%7}, {%8,%9}, {%0,%1,%2,%3};"
        : "+f"(c[0]), "+f"(c[1]), "+f"(c[2]), "+f"(c[3])
        : "r"(a[0]), "r"(a[1]), "r"(a[2]), "r"(a[3]), "r"(b0), "r"(b1));
}
__device__ __forceinline__ void pack_hl_f16(float x, float y, uint32_t& h, uint32_t& l) {
    __half2 hb = __floats2half2_rn(x, y);
    float hx = __low2float(hb), hy = __high2float(hb);
    __half2 lb = __floats2half2_rn(x - hx, y - hy);
    h = *reinterpret_cast<uint32_t*>(&hb);
    l = *reinterpret_cast<uint32_t*>(&lb);
}
__device__ __forceinline__ uint32_t pack_f16(float x, float y) {
    __half2 hb = __floats2half2_rn(x, y);
    return *reinterpret_cast<uint32_t*>(&hb);
}

// ---------------- one fused split: x | wq | wk | wv | wo -> fp16 hi ----------------
#define NX4 (S * DIM / 4)
#define NQ4 (DIM * DIM / 4)
#define NK4 (1024 * DIM / 4)
#define NTOT4 (NX4 + 2 * NQ4 + 2 * NK4)
__global__ void split_all(const float* __restrict__ x,
                          const float* __restrict__ wq, const float* __restrict__ wk,
                          const float* __restrict__ wv, const float* __restrict__ wo,
                          __half* __restrict__ xh, __half* __restrict__ wh,
                          __half* __restrict__ oh)
{
    int i = blockIdx.x * blockDim.x + threadIdx.x;
    if (i >= NTOT4) return;
    const float* src;
    __half* dst;
    int j;
    if (i < NX4)                           { j = i;                       src = x;  dst = xh; }
    else if (i < NX4 + NQ4)                { j = i - NX4;                 src = wq; dst = wh; }
    else if (i < NX4 + NQ4 + NK4)          { j = i - NX4 - NQ4;           src = wk; dst = wh + (size_t)4096 * DIM; }
    else if (i < NX4 + NQ4 + 2 * NK4)      { j = i - NX4 - NQ4 - NK4;     src = wv; dst = wh + (size_t)5120 * DIM; }
    else                                   { j = i - NX4 - NQ4 - 2 * NK4; src = wo; dst = oh; }
    float4 v = ((const float4*)src)[j];
    ((__half2*)dst)[2 * j]     = __floats2half2_rn(v.x, v.y);
    ((__half2*)dst)[2 * j + 1] = __floats2half2_rn(v.z, v.w);
}

// ---------------- fp16 1-term GEMM, CTA 128x128, warp 32x64, 3-stage, 2 CTAs/SM ----
#define GA_HI 0
#define GB_HI (16 * 1024)
#define GSTG  (32 * 1024)
#define GEMM_SMEM (3 * GSTG)

__global__ __launch_bounds__(256, 2) void gemm_f16(
    const __half* __restrict__ Ah, const __half* __restrict__ Bh,
    float* __restrict__ C, int K, int ldc, int mode,
    const float* __restrict__ cs, const float* __restrict__ sn,
    __half* __restrict__ Oh, __half* __restrict__ Ol)
{
    extern __shared__ __align__(1024) char smc[];
    const uint32_t sbase = smem_u32(smc);

    const int tid  = threadIdx.x;
    const int lane = tid & 31;
    const int wid  = tid >> 5;
    const int wm   = wid & 3;
    const int wn   = wid >> 2;
    const int m0 = blockIdx.x * 128;
    const int n0 = blockIdx.y * 128;

    const int grp = lane >> 3;
    const int rin = lane & 7;

    float acc[2][8][4];
    #pragma unroll
    for (int i = 0; i < 2; i++)
        #pragma unroll
        for (int j = 0; j < 8; j++)
            #pragma unroll
            for (int q = 0; q < 4; q++) acc[i][j][q] = 0.f;

    const int nk = K >> 6;

    auto load_chunk = [&](int it) {
        const int k0 = it << 6;
        const uint32_t sb = sbase + (uint32_t)(it % 3) * GSTG;
        #pragma unroll
        for (int i = 0; i < 4; i++) {
            int id = tid + i * 256;
            int row = id >> 3, c16 = id & 7;
            uint32_t so = (uint32_t)(row * 128) + ((uint32_t)(c16 ^ (row & 7)) << 4);
            size_t g = (size_t)(m0 + row) * K + k0 + c16 * 8;
            cp16(sb + GA_HI + so, Ah + g);
        }
        #pragma unroll
        for (int i = 0; i < 4; i++) {
            int id = tid + i * 256;
            int row = id >> 3, c16 = id & 7;
            uint32_t so = (uint32_t)(row * 128) + ((uint32_t)(c16 ^ (row & 7)) << 4);
            size_t g = (size_t)(n0 + row) * K + k0 + c16 * 8;
            cp16(sb + GB_HI + so, Bh + g);
        }
        cp_commit();
    };

    load_chunk(0);
    if (nk > 1) load_chunk(1); else cp_commit();

    for (int it = 0; it < nk; it++) {
        if (it + 2 < nk) load_chunk(it + 2); else cp_commit();
        cp_wait<2>();
        __syncthreads();

        const uint32_t sA = sbase + (uint32_t)(it % 3) * GSTG;
        const uint32_t sB = sA + GB_HI;
        #pragma unroll
        for (int kc = 0; kc < 4; kc++) {
            const int c16 = kc * 2 + (grp >> 1);

            uint32_t ah[2][4];
            #pragma unroll
            for (int am = 0; am < 2; am++) {
                int row = wm * 32 + am * 16 + rin + (grp & 1) * 8;
                uint32_t so = (uint32_t)(row * 128) + ((uint32_t)(c16 ^ (row & 7)) << 4);
                ldm_x4(ah[am], sA + so);
            }
            #pragma unroll
            for (int bt = 0; bt < 4; bt++) {
                int row = wn * 64 + bt * 16 + rin + (grp & 1) * 8;
                uint32_t so = (uint32_t)(row * 128) + ((uint32_t)(c16 ^ (row & 7)) << 4);
                uint32_t bh[4];
                ldm_x4(bh, sB + so);
                #pragma unroll
                for (int am = 0; am < 2; am++) {
                    mma_f16(acc[am][2 * bt],     ah[am], bh[0], bh[2]);
                    mma_f16(acc[am][2 * bt + 1], ah[am], bh[1], bh[3]);
                }
            }
        }
        __syncthreads();
    }

    if (mode == 0) {
        #pragma unroll
        for (int am = 0; am < 2; am++) {
            int row = m0 + wm * 32 + am * 16 + (lane >> 2);
            #pragma unroll
            for (int bn = 0; bn < 8; bn++) {
                int col = n0 + wn * 64 + bn * 8 + (lane & 3) * 2;
                *(float2*)&C[(size_t)row * ldc + col]       = make_float2(acc[am][bn][0], acc[am][bn][1]);
                *(float2*)&C[(size_t)(row + 8) * ldc + col] = make_float2(acc[am][bn][2], acc[am][bn][3]);
            }
        }
    } else {
        #pragma unroll
        for (int am = 0; am < 2; am++) {
            int row = m0 + wm * 32 + am * 16 + (lane >> 2);
            #pragma unroll
            for (int bn = 0; bn < 8; bn++) {
                int col = n0 + wn * 64 + bn * 8 + (lane & 3) * 2;
                int i = (col & (HD - 1)) >> 1;
                bool rope = col < V_OFF;
                #pragma unroll
                for (int half = 0; half < 2; half++) {
                    int r = row + half * 8;
                    float v0 = acc[am][bn][2 * half], v1 = acc[am][bn][2 * half + 1];
                    if (rope) {
                        float c = cs[r * 64 + i], si = sn[r * 64 + i];
                        float t0 = v0 * c - v1 * si;
                        float t1 = v0 * si + v1 * c;
                        v0 = t0; v1 = t1;
                    }
                    uint32_t hb, lb;
                    pack_hl_f16(v0, v1, hb, lb);
                    *(uint32_t*)&Oh[(size_t)r * ldc + col] = hb;
                    *(uint32_t*)&Ol[(size_t)r * ldc + col] = lb;
                }
            }
        }
    }
}

// ---------------- tensor-core flash attention (fp16, causal, GQA 4:1) ----------------
// CTA: 128 threads (4 warps), q-tile 64, 2 CTAs/SM.
// QK^T: (Qh + Ql) * Kh ; PV: P * Vh
// Smem: Qh 16K | Ql 16K | 2 KV stages x (Kh 16K + Vh 16K) = 96KB
#define ATT_SMEM (96 * 1024)

__global__ __launch_bounds__(128, 2) void attn_mma(
    const __half* __restrict__ qh_g, const __half* __restrict__ ql_g,
    __half* __restrict__ ah_g)
{
    extern __shared__ __align__(1024) char smb[];
    const uint32_t sb = smem_u32(smb);
    const uint32_t sQh = sb, sQl = sb + 16 * 1024;

    const int tid = threadIdx.x, lane = tid & 31, wid = tid >> 5;
    const int qt = (int)gridDim.x - 1 - (int)blockIdx.x;
    const int h = blockIdx.y, kvh = h >> 2;
    const int q0 = qt * 64;
    const int wq = wid * 16;

    #pragma unroll
    for (int i = 0; i < 8; i++) {
        int ch = tid + i * 128;
        int row = ch >> 4, c16 = ch & 15;
        uint32_t so = (uint32_t)(row * 256) + (uint32_t)((c16 ^ (row & 7)) << 4);
        size_t g = (size_t)(q0 + row) * QKV_N + h * HD + c16 * 8;
        cp16(sQh + so, qh_g + g);
        cp16(sQl + so, ql_g + g);
    }
    cp_commit();

    const int ktmax = qt;
    auto load_kv = [&](int kt) {
        const uint32_t st = sb + 32 * 1024 + (uint32_t)(kt & 1) * 32 * 1024;
        const int k0 = kt * 64;
        #pragma unroll
        for (int i = 0; i < 8; i++) {
            int ch = tid + i * 128;
            int row = ch >> 4, c16 = ch & 15;
            uint32_t so = (uint32_t)(row * 256) + (uint32_t)((c16 ^ (row & 7)) << 4);
            size_t kb = (size_t)(k0 + row) * QKV_N + kvh * HD + c16 * 8;
            cp16(st + so,             qh_g + kb + K_OFF);
            cp16(st + 16 * 1024 + so, qh_g + kb + V_OFF);
        }
        cp_commit();
    };
    load_kv(0);

    float oacc[16][4];
    #pragma unroll
    for (int a = 0; a < 16; a++)
        #pragma unroll
        for (int q = 0; q < 4; q++) oacc[a][q] = 0.f;
    float m0 = -1e30f, m1 = -1e30f, l0 = 0.f, l1 = 0.f;
    const float kscale = 0.08838834764831845f * 1.44269504088896f;

    const int rin = lane & 7, grp = lane >> 3;
    const int arow = wq + rin + (grp & 1) * 8;
    const int r0 = lane >> 2;

    for (int kt = 0; kt <= ktmax; kt++) {
        if (kt < ktmax) { load_kv(kt + 1); cp_wait<1>(); }
        else            { cp_wait<0>(); }
        __syncthreads();

        {
            const uint32_t st = sb + 32 * 1024 + (uint32_t)(kt & 1) * 32 * 1024;

            float sc[8][4];
            #pragma unroll
            for (int a = 0; a < 8; a++)
                #pragma unroll
                for (int q = 0; q < 4; q++) sc[a][q] = 0.f;

            // QK^T: (Qh + Ql) * Kh
            #pragma unroll
            for (int k16 = 0; k16 < 8; k16++) {
                const int c16 = k16 * 2 + (grp >> 1);
                uint32_t aoff = (uint32_t)(arow * 256) + (uint32_t)((c16 ^ (arow & 7)) << 4);
                uint32_t aqh[4], aql[4];
                ldm_x4(aqh, sQh + aoff);
                ldm_x4(aql, sQl + aoff);
                #pragma unroll
                for (int bp = 0; bp < 2; bp++) {
                    uint32_t bh[2][4];
                    #pragma unroll
                    for (int t = 0; t < 2; t++) {
                        int brow = (bp * 2 + t) * 16 + rin + (grp & 1) * 8;
                        uint32_t boff = (uint32_t)(brow * 256) + (uint32_t)((c16 ^ (brow & 7)) << 4);
                        ldm_x4(bh[t], st + boff);
                    }
                    #pragma unroll
                    for (int t = 0; t < 2; t++) {
                        int b = bp * 2 + t;
                        mma_f16(sc[2 * b],     aqh, bh[t][0], bh[t][2]);
                        mma_f16(sc[2 * b + 1], aqh, bh[t][1], bh[t][3]);
                    }
                    #pragma unroll
                    for (int t = 0; t < 2; t++) {
                        int b = bp * 2 + t;
                        mma_f16(sc[2 * b],     aql, bh[t][0], bh[t][2]);
                        mma_f16(sc[2 * b + 1], aql, bh[t][1], bh[t][3]);
                    }
                }
            }

            if (kt * 64 + 63 > q0 + wq) {
                int qr0 = q0 + wq + r0, qr1 = qr0 + 8;
                int cb = kt * 64 + 2 * (lane & 3);
                #pragma unroll
                for (int a = 0; a < 8; a++) {
                    int c0 = cb + a * 8, c1 = c0 + 1;
                    if (c0 > qr0) sc[a][0] = -1e30f;
                    if (c1 > qr0) sc[a][1] = -1e30f;
                    if (c0 > qr1) sc[a][2] = -1e30f;
                    if (c1 > qr1) sc[a][3] = -1e30f;
                }
            }

            float mx0 = -1e30f, mx1 = -1e30f;
            #pragma unroll
            for (int a = 0; a < 8; a++) {
                mx0 = fmaxf(mx0, fmaxf(sc[a][0], sc[a][1]));
                mx1 = fmaxf(mx1, fmaxf(sc[a][2], sc[a][3]));
            }
            mx0 = fmaxf(mx0, __shfl_xor_sync(0xffffffffu, mx0, 1));
            mx0 = fmaxf(mx0, __shfl_xor_sync(0xffffffffu, mx0, 2));
            mx1 = fmaxf(mx1, __shfl_xor_sync(0xffffffffu, mx1, 1));
            mx1 = fmaxf(mx1, __shfl_xor_sync(0xffffffffu, mx1, 2));
            float nm0 = fmaxf(m0, mx0), nm1 = fmaxf(m1, mx1);
            float corr0 = exp2f((m0 - nm0) * kscale);
            float corr1 = exp2f((m1 - nm1) * kscale);
            float s0 = 0.f, s1 = 0.f;
            #pragma unroll
            for (int a = 0; a < 8; a++) {
                sc[a][0] = exp2f((sc[a][0] - nm0) * kscale);
                sc[a][1] = exp2f((sc[a][1] - nm0) * kscale);
                sc[a][2] = exp2f((sc[a][2] - nm1) * kscale);
                sc[a][3] = exp2f((sc[a][3] - nm1) * kscale);
                s0 += sc[a][0] + sc[a][1];
                s1 += sc[a][2] + sc[a][3];
            }
            s0 += __shfl_xor_sync(0xffffffffu, s0, 1);
            s0 += __shfl_xor_sync(0xffffffffu, s0, 2);
            s1 += __shfl_xor_sync(0xffffffffu, s1, 1);
            s1 += __shfl_xor_sync(0xffffffffu, s1, 2);
            l0 = l0 * corr0 + s0;
            l1 = l1 * corr1 + s1;
            m0 = nm0; m1 = nm1;
            #pragma unroll
            for (int a = 0; a < 16; a++) {
                oacc[a][0] *= corr0; oacc[a][1] *= corr0;
                oacc[a][2] *= corr1; oacc[a][3] *= corr1;
            }

            // PV: P * Vh
            #pragma unroll
            for (int t = 0; t < 4; t++) {
                uint32_t ph[4];
                ph[0] = pack_f16(sc[2 * t][0],     sc[2 * t][1]);
                ph[1] = pack_f16(sc[2 * t][2],     sc[2 * t][3]);
                ph[2] = pack_f16(sc[2 * t + 1][0], sc[2 * t + 1][1]);
                ph[3] = pack_f16(sc[2 * t + 1][2], sc[2 * t + 1][3]);
                #pragma unroll
                for (int dp = 0; dp < 4; dp++) {
                    uint32_t vh[2][4];
                    #pragma unroll
                    for (int u = 0; u < 2; u++) {
                        int d = dp * 2 + u;
                        int vrow = t * 16 + (grp & 1) * 8 + rin;
                        int c16 = d * 2 + (grp >> 1);
                        uint32_t voff = (uint32_t)(vrow * 256) + (uint32_t)((c16 ^ (vrow & 7)) << 4);
                        ldm_x4t(vh[u], st + 16 * 1024 + voff);
                    }
                    #pragma unroll
                    for (int u = 0; u < 2; u++) {
                        int d = dp * 2 + u;
                        mma_f16(oacc[2 * d],     ph, vh[u][0], vh[u][1]);
                        mma_f16(oacc[2 * d + 1], ph, vh[u][2], vh[u][3]);
                    }
                }
            }
        }
        __syncthreads();
    }

    float inv0 = 1.f / l0, inv1 = 1.f / l1;
    int gr0 = q0 + wq + r0, gr1 = gr0 + 8;
    #pragma unroll
    for (int a = 0; a < 16; a++) {
        int d0 = a * 8 + 2 * (lane & 3);
        *(uint32_t*)&ah_g[(size_t)gr0 * DIM + h * HD + d0] =
            pack_f16(oacc[a][0] * inv0, oacc[a][1] * inv0);
        *(uint32_t*)&ah_g[(size_t)gr1 * DIM + h * HD + d0] =
            pack_f16(oacc[a][2] * inv1, oacc[a][3] * inv1);
    }
}

// ---------------- launch ----------------
extern "C" void kernel_launch(void* const* d_in, const int* in_sizes, int n_in,
                              void* d_out, int out_size)
{
    const float* x  = (const float*)d_in[0];
    const float* fc = (const float*)d_in[1];
    const float* fs = (const float*)d_in[2];
    const float* wq = (const float*)d_in[5];
    const float* wk = (const float*)d_in[6];
    const float* wv = (const float*)d_in[7];
    const float* wo = (const float*)d_in[8];
    float* out = (float*)d_out;

    __half *qh, *ql, *xh, *wh, *oh, *ah;
    cudaGetSymbolAddress((void**)&qh, g_qh);  cudaGetSymbolAddress((void**)&ql, g_ql);
    cudaGetSymbolAddress((void**)&xh, g_xh);
    cudaGetSymbolAddress((void**)&wh, g_wh);  cudaGetSymbolAddress((void**)&oh, g_oh);
    cudaGetSymbolAddress((void**)&ah, g_ah);

    cudaFuncSetAttribute(gemm_f16, cudaFuncAttributeMaxDynamicSharedMemorySize, GEMM_SMEM);
    cudaFuncSetAttribute(attn_mma, cudaFuncAttributeMaxDynamicSharedMemorySize, ATT_SMEM);

    dim3 blk(256);
    split_all<<<(NTOT4 + 255) / 256, blk>>>(x, wq, wk, wv, wo, xh, wh, oh);

    // QKV projection (fp16 1-term) with fused RoPE + fp16 hi/lo split epilogue
    gemm_f16<<<dim3(S / 128, QKV_N / 128), blk, GEMM_SMEM>>>(
        xh, wh, nullptr, DIM, QKV_N, 1, fc, fs, qh, ql);

    // tensor-core attention (fp16), 4-warp CTAs, 2 CTAs/SM
    attn_mma<<<dim3(S / 64, NH), dim3(128), ATT_SMEM>>>(qh, ql, ah);

    // output projection (fp16 1-term) -> fp32 out
    gemm_f16<<<dim3(S / 128, DIM / 128), blk, GEMM_SMEM>>>(
        ah, oh, out, DIM, DIM, 0, nullptr, nullptr, nullptr, nullptr);
}

// round 16
// speedup vs baseline: 1.5886x; 1.0379x over previous
#include <cuda_runtime.h>
#include <cuda_bf16.h>
#include <cuda_fp16.h>
#include <cstdint>

// ---------------- problem constants ----------------
#define S       2048
#define DIM     4096
#define NH      32
#define HD      128
#define QKV_N   6144
#define K_OFF   4096
#define V_OFF   5120
#define GK      4096            // K dim of both GEMMs (== DIM)

// ---------------- scratch (device globals) ----------------
__device__ __half g_qh[S * QKV_N], g_ql[S * QKV_N];   // rope'd qkv, fp16 hi/lo
__device__ __half g_xh[S * DIM];                      // x fp16 hi
__device__ __half g_wh[QKV_N * DIM];                  // packed wq|wk|wv fp16 hi
__device__ __half g_oh[DIM * DIM];                    // wo fp16 hi
__device__ __half g_ah[S * DIM];                      // attention out fp16 hi

// ---------------- helpers ----------------
__device__ __forceinline__ uint32_t smem_u32(const void* p) {
    uint32_t a;
    asm("{ .reg .u64 t; cvta.to.shared.u64 t, %1; cvt.u32.u64 %0, t; }" : "=r"(a) : "l"(p));
    return a;
}
__device__ __forceinline__ void cp16(uint32_t dst, const void* src) {
    asm volatile("cp.async.cg.shared.global [%0], [%1], 16;" :: "r"(dst), "l"(src));
}
__device__ __forceinline__ void cp_commit() {
    asm volatile("cp.async.commit_group;");
}
template <int N>
__device__ __forceinline__ void cp_wait() {
    asm volatile("cp.async.wait_group %0;" :: "n"(N));
}
__device__ __forceinline__ void ldm_x4(uint32_t* r, uint32_t addr) {
    asm volatile("ldmatrix.sync.aligned.m8n8.x4.shared.b16 {%0,%1,%2,%3}, [%4];"
                 : "=r"(r[0]), "=r"(r[1]), "=r"(r[2]), "=r"(r[3]) : "r"(addr));
}
__device__ __forceinline__ void ldm_x4t(uint32_t* r, uint32_t addr) {
    asm volatile("ldmatrix.sync.aligned.m8n8.x4.trans.shared.b16 {%0,%1,%2,%3}, [%4];"
                 : "=r"(r[0]), "=r"(r[1]), "=r"(r[2]), "=r"(r[3]) : "r"(addr));
}
__device__ __forceinline__ void mma_f16(float* c, const uint32_t* a, uint32_t b0, uint32_t b1) {
    asm volatile(
        "mma.sync.aligned.m16n8k16.row.col.f32.f16.f16.f32 "
        "{%0,%1,%2,%3}, {%4,%5,%6,%7}, {%8,%9}, {%0,%1,%2,%3};"
        : "+f"(c[0]), "+f"(c[1]), "+f"(c[2]), "+f"(c[3])
        : "r"(a[0]), "r"(a[1]), "r"(a[2]), "r"(a[3]), "r"(b0), "r"(b1));
}
__device__ __forceinline__ void pack_hl_f16(float x, float y, uint32_t& h, uint32_t& l) {
    __half2 hb = __floats2half2_rn(x, y);
    float hx = __low2float(hb), hy = __high2float(hb);
    __half2 lb = __floats2half2_rn(x - hx, y - hy);
    h = *reinterpret_cast<uint32_t*>(&hb);
    l = *reinterpret_cast<uint32_t*>(&lb);
}
__device__ __forceinline__ uint32_t pack_f16(float x, float y) {
    __half2 hb = __floats2half2_rn(x, y);
    return *reinterpret_cast<uint32_t*>(&hb);
}

// ---------------- one fused split: x | wq | wk | wv | wo -> fp16 hi ----------------
#define NX4 (S * DIM / 4)
#define NQ4 (DIM * DIM / 4)
#define NK4 (1024 * DIM / 4)
#define NTOT4 (NX4 + 2 * NQ4 + 2 * NK4)
__global__ void split_all(const float* __restrict__ x,
                          const float* __restrict__ wq, const float* __restrict__ wk,
                          const float* __restrict__ wv, const float* __restrict__ wo,
                          __half* __restrict__ xh, __half* __restrict__ wh,
                          __half* __restrict__ oh)
{
    int i = blockIdx.x * blockDim.x + threadIdx.x;
    if (i >= NTOT4) return;
    const float* src;
    __half* dst;
    int j;
    if (i < NX4)                           { j = i;                       src = x;  dst = xh; }
    else if (i < NX4 + NQ4)                { j = i - NX4;                 src = wq; dst = wh; }
    else if (i < NX4 + NQ4 + NK4)          { j = i - NX4 - NQ4;           src = wk; dst = wh + (size_t)4096 * DIM; }
    else if (i < NX4 + NQ4 + 2 * NK4)      { j = i - NX4 - NQ4 - NK4;     src = wv; dst = wh + (size_t)5120 * DIM; }
    else                                   { j = i - NX4 - NQ4 - 2 * NK4; src = wo; dst = oh; }
    float4 v = ((const float4*)src)[j];
    ((__half2*)dst)[2 * j]     = __floats2half2_rn(v.x, v.y);
    ((__half2*)dst)[2 * j + 1] = __floats2half2_rn(v.z, v.w);
}

// ---------------- fp16 1-term GEMM, CTA 128x128, warp 32x64, 3-stage, 2 CTAs/SM ----
// Single-sync pipeline; hoisted addresses; K hardcoded 4096.
#define GA_HI 0
#define GB_HI (16 * 1024)
#define GSTG  (32 * 1024)
#define GEMM_SMEM (3 * GSTG)

__global__ __launch_bounds__(256, 2) void gemm_f16(
    const __half* __restrict__ Ah, const __half* __restrict__ Bh,
    float* __restrict__ C, int ldc, int mode,
    const float* __restrict__ cs, const float* __restrict__ sn,
    __half* __restrict__ Oh, __half* __restrict__ Ol)
{
    extern __shared__ __align__(1024) char smc[];
    const uint32_t sbase = smem_u32(smc);

    const int tid  = threadIdx.x;
    const int lane = tid & 31;
    const int wid  = tid >> 5;
    const int wm   = wid & 3;
    const int wn   = wid >> 2;
    const int m0 = blockIdx.x * 128;
    const int n0 = blockIdx.y * 128;

    const int grp = lane >> 3;
    const int rin = lane & 7;

    // ---- hoisted global-load mapping ----
    const int gRow = tid >> 3;                    // 0..31
    const int gc8  = (tid & 7) * 8;               // element col
    const uint32_t soBase = (uint32_t)(gRow * 128)
                          + ((uint32_t)((tid & 7) ^ (gRow & 7)) << 4);
    const __half* aP = Ah + (size_t)(m0 + gRow) * GK + gc8;
    const __half* bP = Bh + (size_t)(n0 + gRow) * GK + gc8;

    // ---- hoisted ldsm row bases ----
    uint32_t baseA[2]; int swA[2];
    #pragma unroll
    for (int am = 0; am < 2; am++) {
        int r = wm * 32 + am * 16 + rin + (grp & 1) * 8;
        baseA[am] = (uint32_t)(r * 128);
        swA[am] = r & 7;
    }
    uint32_t baseB[4]; int swB[4];
    #pragma unroll
    for (int bt = 0; bt < 4; bt++) {
        int r = wn * 64 + bt * 16 + rin + (grp & 1) * 8;
        baseB[bt] = (uint32_t)(r * 128);
        swB[bt] = r & 7;
    }

    float acc[2][8][4];
    #pragma unroll
    for (int i = 0; i < 2; i++)
        #pragma unroll
        for (int j = 0; j < 8; j++)
            #pragma unroll
            for (int q = 0; q < 4; q++) acc[i][j][q] = 0.f;

    const int nk = GK >> 6;   // 64

    auto load_chunk = [&](int it) {
        const int k0 = it << 6;
        const uint32_t sb = sbase + (uint32_t)(it % 3) * GSTG;
        #pragma unroll
        for (int i = 0; i < 4; i++) {
            cp16(sb + GA_HI + soBase + (uint32_t)(i * 4096), aP + k0 + i * 32 * GK);
            cp16(sb + GB_HI + soBase + (uint32_t)(i * 4096), bP + k0 + i * 32 * GK);
        }
        cp_commit();
    };

    load_chunk(0);
    load_chunk(1);

    for (int it = 0; it < nk; it++) {
        if (it < nk - 1) cp_wait<1>(); else cp_wait<0>();
        __syncthreads();
        if (it + 2 < nk) load_chunk(it + 2);

        const uint32_t sA = sbase + (uint32_t)(it % 3) * GSTG;
        const uint32_t sB = sA + GB_HI;
        #pragma unroll
        for (int kc = 0; kc < 4; kc++) {
            const int c16 = kc * 2 + (grp >> 1);

            uint32_t ah[2][4];
            #pragma unroll
            for (int am = 0; am < 2; am++)
                ldm_x4(ah[am], sA + baseA[am] + ((uint32_t)(c16 ^ swA[am]) << 4));
            #pragma unroll
            for (int bt = 0; bt < 4; bt++) {
                uint32_t bh[4];
                ldm_x4(bh, sB + baseB[bt] + ((uint32_t)(c16 ^ swB[bt]) << 4));
                #pragma unroll
                for (int am = 0; am < 2; am++) {
                    mma_f16(acc[am][2 * bt],     ah[am], bh[0], bh[2]);
                    mma_f16(acc[am][2 * bt + 1], ah[am], bh[1], bh[3]);
                }
            }
        }
    }

    if (mode == 0) {
        #pragma unroll
        for (int am = 0; am < 2; am++) {
            int row = m0 + wm * 32 + am * 16 + (lane >> 2);
            #pragma unroll
            for (int bn = 0; bn < 8; bn++) {
                int col = n0 + wn * 64 + bn * 8 + (lane & 3) * 2;
                *(float2*)&C[(size_t)row * ldc + col]       = make_float2(acc[am][bn][0], acc[am][bn][1]);
                *(float2*)&C[(size_t)(row + 8) * ldc + col] = make_float2(acc[am][bn][2], acc[am][bn][3]);
            }
        }
    } else {
        #pragma unroll
        for (int am = 0; am < 2; am++) {
            int row = m0 + wm * 32 + am * 16 + (lane >> 2);
            #pragma unroll
            for (int bn = 0; bn < 8; bn++) {
                int col = n0 + wn * 64 + bn * 8 + (lane & 3) * 2;
                int i = (col & (HD - 1)) >> 1;
                bool rope = col < V_OFF;
                #pragma unroll
                for (int half = 0; half < 2; half++) {
                    int r = row + half * 8;
                    float v0 = acc[am][bn][2 * half], v1 = acc[am][bn][2 * half + 1];
                    if (rope) {
                        float c = cs[r * 64 + i], si = sn[r * 64 + i];
                        float t0 = v0 * c - v1 * si;
                        float t1 = v0 * si + v1 * c;
                        v0 = t0; v1 = t1;
                    }
                    uint32_t hb, lb;
                    pack_hl_f16(v0, v1, hb, lb);
                    *(uint32_t*)&Oh[(size_t)r * ldc + col] = hb;
                    *(uint32_t*)&Ol[(size_t)r * ldc + col] = lb;
                }
            }
        }
    }
}

// ---------------- tensor-core flash attention (fp16, causal, GQA 4:1) ----------------
// CTA: 128 threads (4 warps), q-tile 64, 2 CTAs/SM, single-sync pipeline.
// QK^T: (Qh + Ql) * Kh ; PV: P * Vh
#define ATT_SMEM (96 * 1024)

__global__ __launch_bounds__(128, 2) void attn_mma(
    const __half* __restrict__ qh_g, const __half* __restrict__ ql_g,
    __half* __restrict__ ah_g)
{
    extern __shared__ __align__(1024) char smb[];
    const uint32_t sb = smem_u32(smb);
    const uint32_t sQh = sb, sQl = sb + 16 * 1024;

    const int tid = threadIdx.x, lane = tid & 31, wid = tid >> 5;
    const int qt = (int)gridDim.x - 1 - (int)blockIdx.x;
    const int h = blockIdx.y, kvh = h >> 2;
    const int q0 = qt * 64;
    const int wq = wid * 16;

    // hoisted KV load mapping
    const int kRow = tid >> 4;                 // 0..7
    const int kc16 = tid & 15;
    const uint32_t soK = (uint32_t)(kRow * 256)
                       + ((uint32_t)(kc16 ^ (kRow & 7)) << 4);
    const __half* kP = qh_g + (size_t)kRow * QKV_N + kvh * HD + kc16 * 8 + K_OFF;
    const __half* vP = kP + (V_OFF - K_OFF);

    // Q tile load
    #pragma unroll
    for (int i = 0; i < 8; i++) {
        int ch = tid + i * 128;
        int row = ch >> 4, c16 = ch & 15;
        uint32_t so = (uint32_t)(row * 256) + (uint32_t)((c16 ^ (row & 7)) << 4);
        size_t g = (size_t)(q0 + row) * QKV_N + h * HD + c16 * 8;
        cp16(sQh + so, qh_g + g);
        cp16(sQl + so, ql_g + g);
    }
    cp_commit();

    const int ktmax = qt;
    auto load_kv = [&](int kt) {
        const uint32_t st = sb + 32 * 1024 + (uint32_t)(kt & 1) * 32 * 1024;
        const size_t koff = (size_t)kt * 64 * QKV_N;
        #pragma unroll
        for (int i = 0; i < 8; i++) {
            cp16(st + soK + (uint32_t)(i * 2048),             kP + koff + (size_t)i * 8 * QKV_N);
            cp16(st + 16 * 1024 + soK + (uint32_t)(i * 2048), vP + koff + (size_t)i * 8 * QKV_N);
        }
        cp_commit();
    };
    load_kv(0);

    float oacc[16][4];
    #pragma unroll
    for (int a = 0; a < 16; a++)
        #pragma unroll
        for (int q = 0; q < 4; q++) oacc[a][q] = 0.f;
    float m0 = -1e30f, m1 = -1e30f, l0 = 0.f, l1 = 0.f;
    const float kscale = 0.08838834764831845f * 1.44269504088896f;

    const int rin = lane & 7, grp = lane >> 3;
    const int arow = wq + rin + (grp & 1) * 8;
    const int r0 = lane >> 2;

    for (int kt = 0; kt <= ktmax; kt++) {
        cp_wait<0>();
        __syncthreads();
        if (kt < ktmax) load_kv(kt + 1);

        {
            const uint32_t st = sb + 32 * 1024 + (uint32_t)(kt & 1) * 32 * 1024;

            float sc[8][4];
            #pragma unroll
            for (int a = 0; a < 8; a++)
                #pragma unroll
                for (int q = 0; q < 4; q++) sc[a][q] = 0.f;

            // QK^T: (Qh + Ql) * Kh
            #pragma unroll
            for (int k16 = 0; k16 < 8; k16++) {
                const int c16 = k16 * 2 + (grp >> 1);
                uint32_t aoff = (uint32_t)(arow * 256) + (uint32_t)((c16 ^ (arow & 7)) << 4);
                uint32_t aqh[4], aql[4];
                ldm_x4(aqh, sQh + aoff);
                ldm_x4(aql, sQl + aoff);
                #pragma unroll
                for (int bp = 0; bp < 2; bp++) {
                    uint32_t bh[2][4];
                    #pragma unroll
                    for (int t = 0; t < 2; t++) {
                        int brow = (bp * 2 + t) * 16 + rin + (grp & 1) * 8;
                        uint32_t boff = (uint32_t)(brow * 256) + (uint32_t)((c16 ^ (brow & 7)) << 4);
                        ldm_x4(bh[t], st + boff);
                    }
                    #pragma unroll
                    for (int t = 0; t < 2; t++) {
                        int b = bp * 2 + t;
                        mma_f16(sc[2 * b],     aqh, bh[t][0], bh[t][2]);
                        mma_f16(sc[2 * b + 1], aqh, bh[t][1], bh[t][3]);
                    }
                    #pragma unroll
                    for (int t = 0; t < 2; t++) {
                        int b = bp * 2 + t;
                        mma_f16(sc[2 * b],     aql, bh[t][0], bh[t][2]);
                        mma_f16(sc[2 * b + 1], aql, bh[t][1], bh[t][3]);
                    }
                }
            }

            if (kt * 64 + 63 > q0 + wq) {
                int qr0 = q0 + wq + r0, qr1 = qr0 + 8;
                int cb = kt * 64 + 2 * (lane & 3);
                #pragma unroll
                for (int a = 0; a < 8; a++) {
                    int c0 = cb + a * 8, c1 = c0 + 1;
                    if (c0 > qr0) sc[a][0] = -1e30f;
                    if (c1 > qr0) sc[a][1] = -1e30f;
                    if (c0 > qr1) sc[a][2] = -1e30f;
                    if (c1 > qr1) sc[a][3] = -1e30f;
                }
            }

            float mx0 = -1e30f, mx1 = -1e30f;
            #pragma unroll
            for (int a = 0; a < 8; a++) {
                mx0 = fmaxf(mx0, fmaxf(sc[a][0], sc[a][1]));
                mx1 = fmaxf(mx1, fmaxf(sc[a][2], sc[a][3]));
            }
            mx0 = fmaxf(mx0, __shfl_xor_sync(0xffffffffu, mx0, 1));
            mx0 = fmaxf(mx0, __shfl_xor_sync(0xffffffffu, mx0, 2));
            mx1 = fmaxf(mx1, __shfl_xor_sync(0xffffffffu, mx1, 1));
            mx1 = fmaxf(mx1, __shfl_xor_sync(0xffffffffu, mx1, 2));
            float nm0 = fmaxf(m0, mx0), nm1 = fmaxf(m1, mx1);
            float corr0 = exp2f((m0 - nm0) * kscale);
            float corr1 = exp2f((m1 - nm1) * kscale);
            float s0 = 0.f, s1 = 0.f;
            #pragma unroll
            for (int a = 0; a < 8; a++) {
                sc[a][0] = exp2f((sc[a][0] - nm0) * kscale);
                sc[a][1] = exp2f((sc[a][1] - nm0) * kscale);
                sc[a][2] = exp2f((sc[a][2] - nm1) * kscale);
                sc[a][3] = exp2f((sc[a][3] - nm1) * kscale);
                s0 += sc[a][0] + sc[a][1];
                s1 += sc[a][2] + sc[a][3];
            }
            s0 += __shfl_xor_sync(0xffffffffu, s0, 1);
            s0 += __shfl_xor_sync(0xffffffffu, s0, 2);
            s1 += __shfl_xor_sync(0xffffffffu, s1, 1);
            s1 += __shfl_xor_sync(0xffffffffu, s1, 2);
            l0 = l0 * corr0 + s0;
            l1 = l1 * corr1 + s1;
            m0 = nm0; m1 = nm1;
            #pragma unroll
            for (int a = 0; a < 16; a++) {
                oacc[a][0] *= corr0; oacc[a][1] *= corr0;
                oacc[a][2] *= corr1; oacc[a][3] *= corr1;
            }

            // PV: P * Vh
            #pragma unroll
            for (int t = 0; t < 4; t++) {
                uint32_t ph[4];
                ph[0] = pack_f16(sc[2 * t][0],     sc[2 * t][1]);
                ph[1] = pack_f16(sc[2 * t][2],     sc[2 * t][3]);
                ph[2] = pack_f16(sc[2 * t + 1][0], sc[2 * t + 1][1]);
                ph[3] = pack_f16(sc[2 * t + 1][2], sc[2 * t + 1][3]);
                #pragma unroll
                for (int dp = 0; dp < 4; dp++) {
                    uint32_t vh[2][4];
                    #pragma unroll
                    for (int u = 0; u < 2; u++) {
                        int d = dp * 2 + u;
                        int vrow = t * 16 + (grp & 1) * 8 + rin;
                        int c16 = d * 2 + (grp >> 1);
                        uint32_t voff = (uint32_t)(vrow * 256) + (uint32_t)((c16 ^ (vrow & 7)) << 4);
                        ldm_x4t(vh[u], st + 16 * 1024 + voff);
                    }
                    #pragma unroll
                    for (int u = 0; u < 2; u++) {
                        int d = dp * 2 + u;
                        mma_f16(oacc[2 * d],     ph, vh[u][0], vh[u][1]);
                        mma_f16(oacc[2 * d + 1], ph, vh[u][2], vh[u][3]);
                    }
                }
            }
        }
    }

    float inv0 = 1.f / l0, inv1 = 1.f / l1;
    int gr0 = q0 + wq + r0, gr1 = gr0 + 8;
    #pragma unroll
    for (int a = 0; a < 16; a++) {
        int d0 = a * 8 + 2 * (lane & 3);
        *(uint32_t*)&ah_g[(size_t)gr0 * DIM + h * HD + d0] =
            pack_f16(oacc[a][0] * inv0, oacc[a][1] * inv0);
        *(uint32_t*)&ah_g[(size_t)gr1 * DIM + h * HD + d0] =
            pack_f16(oacc[a][2] * inv1, oacc[a][3] * inv1);
    }
}

// ---------------- launch ----------------
extern "C" void kernel_launch(void* const* d_in, const int* in_sizes, int n_in,
                              void* d_out, int out_size)
{
    const float* x  = (const float*)d_in[0];
    const float* fc = (const float*)d_in[1];
    const float* fs = (const float*)d_in[2];
    const float* wq = (const float*)d_in[5];
    const float* wk = (const float*)d_in[6];
    const float* wv = (const float*)d_in[7];
    const float* wo = (const float*)d_in[8];
    float* out = (float*)d_out;

    __half *qh, *ql, *xh, *wh, *oh, *ah;
    cudaGetSymbolAddress((void**)&qh, g_qh);  cudaGetSymbolAddress((void**)&ql, g_ql);
    cudaGetSymbolAddress((void**)&xh, g_xh);
    cudaGetSymbolAddress((void**)&wh, g_wh);  cudaGetSymbolAddress((void**)&oh, g_oh);
    cudaGetSymbolAddress((void**)&ah, g_ah);

    cudaFuncSetAttribute(gemm_f16, cudaFuncAttributeMaxDynamicSharedMemorySize, GEMM_SMEM);
    cudaFuncSetAttribute(attn_mma, cudaFuncAttributeMaxDynamicSharedMemorySize, ATT_SMEM);

    dim3 blk(256);
    split_all<<<(NTOT4 + 255) / 256, blk>>>(x, wq, wk, wv, wo, xh, wh, oh);

    // QKV projection (fp16 1-term) with fused RoPE + fp16 hi/lo split epilogue
    gemm_f16<<<dim3(S / 128, QKV_N / 128), blk, GEMM_SMEM>>>(
        xh, wh, nullptr, QKV_N, 1, fc, fs, qh, ql);

    // tensor-core attention (fp16), 4-warp CTAs, 2 CTAs/SM
    attn_mma<<<dim3(S / 64, NH), dim3(128), ATT_SMEM>>>(qh, ql, ah);

    // output projection (fp16 1-term) -> fp32 out
    gemm_f16<<<dim3(S / 128, DIM / 128), blk, GEMM_SMEM>>>(
        ah, oh, out, DIM, 0, nullptr, nullptr, nullptr, nullptr);
}

// round 17
// speedup vs baseline: 1.7235x; 1.0849x over previous
#include <cuda_runtime.h>
#include <cuda_bf16.h>
#include <cuda_fp16.h>
#include <cstdint>

// ---------------- problem constants ----------------
#define S       2048
#define DIM     4096
#define NH      32
#define HD      128
#define QKV_N   6144
#define K_OFF   4096
#define V_OFF   5120
#define GK      4096

// ---------------- scratch (device globals) ----------------
__device__ __half g_qh[S * QKV_N], g_ql[S * QKV_N];
__device__ __half g_xh[S * DIM];
__device__ __half g_wh[QKV_N * DIM];
__device__ __half g_oh[DIM * DIM];
__device__ __half g_ah[S * DIM];

// ---------------- helpers ----------------
__device__ __forceinline__ uint32_t smem_u32(const void* p) {
    uint32_t a;
    asm("{ .reg .u64 t; cvta.to.shared.u64 t, %1; cvt.u32.u64 %0, t; }" : "=r"(a) : "l"(p));
    return a;
}
__device__ __forceinline__ void cp16(uint32_t dst, const void* src) {
    asm volatile("cp.async.cg.shared.global [%0], [%1], 16;" :: "r"(dst), "l"(src));
}
__device__ __forceinline__ void cp_commit() {
    asm volatile("cp.async.commit_group;");
}
template <int N>
__device__ __forceinline__ void cp_wait() {
    asm volatile("cp.async.wait_group %0;" :: "n"(N));
}
__device__ __forceinline__ void ldm_x4(uint32_t* r, uint32_t addr) {
    asm volatile("ldmatrix.sync.aligned.m8n8.x4.shared.b16 {%0,%1,%2,%3}, [%4];"
                 : "=r"(r[0]), "=r"(r[1]), "=r"(r[2]), "=r"(r[3]) : "r"(addr));
}
__device__ __forceinline__ void ldm_x4t(uint32_t* r, uint32_t addr) {
    asm volatile("ldmatrix.sync.aligned.m8n8.x4.trans.shared.b16 {%0,%1,%2,%3}, [%4];"
                 : "=r"(r[0]), "=r"(r[1]), "=r"(r[2]), "=r"(r[3]) : "r"(addr));
}
__device__ __forceinline__ void mma_f16(float* c, const uint32_t* a, uint32_t b0, uint32_t b1) {
    asm volatile(
        "mma.sync.aligned.m16n8k16.row.col.f32.f16.f16.f32 "
        "{%0,%1,%2,%3}, {%4,%5,%6,%7}, {%8,%9}, {%0,%1,%2,%3};"
        : "+f"(c[0]), "+f"(c[1]), "+f"(c[2]), "+f"(c[3])
        : "r"(a[0]), "r"(a[1]), "r"(a[2]), "r"(a[3]), "r"(b0), "r"(b1));
}
__device__ __forceinline__ void pack_hl_f16(float x, float y, uint32_t& h, uint32_t& l) {
    __half2 hb = __floats2half2_rn(x, y);
    float hx = __low2float(hb), hy = __high2float(hb);
    __half2 lb = __floats2half2_rn(x - hx, y - hy);
    h = *reinterpret_cast<uint32_t*>(&hb);
    l = *reinterpret_cast<uint32_t*>(&lb);
}
__device__ __forceinline__ uint32_t pack_f16(float x, float y) {
    __half2 hb = __floats2half2_rn(x, y);
    return *reinterpret_cast<uint32_t*>(&hb);
}

// ---------------- one fused split: x | wq | wk | wv | wo -> fp16 hi ----------------
#define NX4 (S * DIM / 4)
#define NQ4 (DIM * DIM / 4)
#define NK4 (1024 * DIM / 4)
#define NTOT4 (NX4 + 2 * NQ4 + 2 * NK4)
__global__ void split_all(const float* __restrict__ x,
                          const float* __restrict__ wq, const float* __restrict__ wk,
                          const float* __restrict__ wv, const float* __restrict__ wo,
                          __half* __restrict__ xh, __half* __restrict__ wh,
                          __half* __restrict__ oh)
{
    int i = blockIdx.x * blockDim.x + threadIdx.x;
    if (i >= NTOT4) return;
    const float* src;
    __half* dst;
    int j;
    if (i < NX4)                           { j = i;                       src = x;  dst = xh; }
    else if (i < NX4 + NQ4)                { j = i - NX4;                 src = wq; dst = wh; }
    else if (i < NX4 + NQ4 + NK4)          { j = i - NX4 - NQ4;           src = wk; dst = wh + (size_t)4096 * DIM; }
    else if (i < NX4 + NQ4 + 2 * NK4)      { j = i - NX4 - NQ4 - NK4;     src = wv; dst = wh + (size_t)5120 * DIM; }
    else                                   { j = i - NX4 - NQ4 - 2 * NK4; src = wo; dst = oh; }
    float4 v = ((const float4*)src)[j];
    ((__half2*)dst)[2 * j]     = __floats2half2_rn(v.x, v.y);
    ((__half2*)dst)[2 * j + 1] = __floats2half2_rn(v.z, v.w);
}

// ---------------- fp16 1-term GEMM, CTA 128x128, warp 32x64, 3-stage, 2 CTAs/SM ----
#define GA_HI 0
#define GB_HI (16 * 1024)
#define GSTG  (32 * 1024)
#define GEMM_SMEM (3 * GSTG)

__global__ __launch_bounds__(256, 2) void gemm_f16(
    const __half* __restrict__ Ah, const __half* __restrict__ Bh,
    float* __restrict__ C, int ldc, int mode, int mbase,
    const float* __restrict__ cs, const float* __restrict__ sn,
    __half* __restrict__ Oh, __half* __restrict__ Ol)
{
    extern __shared__ __align__(1024) char smc[];
    const uint32_t sbase = smem_u32(smc);

    const int tid  = threadIdx.x;
    const int lane = tid & 31;
    const int wid  = tid >> 5;
    const int wm   = wid & 3;
    const int wn   = wid >> 2;
    const int m0 = mbase + blockIdx.x * 128;
    const int n0 = blockIdx.y * 128;

    const int grp = lane >> 3;
    const int rin = lane & 7;

    const int gRow = tid >> 3;
    const int gc8  = (tid & 7) * 8;
    const uint32_t soBase = (uint32_t)(gRow * 128)
                          + ((uint32_t)((tid & 7) ^ (gRow & 7)) << 4);
    const __half* aP = Ah + (size_t)(m0 + gRow) * GK + gc8;
    const __half* bP = Bh + (size_t)(n0 + gRow) * GK + gc8;

    uint32_t baseA[2]; int swA[2];
    #pragma unroll
    for (int am = 0; am < 2; am++) {
        int r = wm * 32 + am * 16 + rin + (grp & 1) * 8;
        baseA[am] = (uint32_t)(r * 128);
        swA[am] = r & 7;
    }
    uint32_t baseB[4]; int swB[4];
    #pragma unroll
    for (int bt = 0; bt < 4; bt++) {
        int r = wn * 64 + bt * 16 + rin + (grp & 1) * 8;
        baseB[bt] = (uint32_t)(r * 128);
        swB[bt] = r & 7;
    }

    float acc[2][8][4];
    #pragma unroll
    for (int i = 0; i < 2; i++)
        #pragma unroll
        for (int j = 0; j < 8; j++)
            #pragma unroll
            for (int q = 0; q < 4; q++) acc[i][j][q] = 0.f;

    const int nk = GK >> 6;

    auto load_chunk = [&](int it) {
        const int k0 = it << 6;
        const uint32_t sb = sbase + (uint32_t)(it % 3) * GSTG;
        #pragma unroll
        for (int i = 0; i < 4; i++) {
            cp16(sb + GA_HI + soBase + (uint32_t)(i * 4096), aP + k0 + i * 32 * GK);
            cp16(sb + GB_HI + soBase + (uint32_t)(i * 4096), bP + k0 + i * 32 * GK);
        }
        cp_commit();
    };

    load_chunk(0);
    load_chunk(1);

    for (int it = 0; it < nk; it++) {
        if (it < nk - 1) cp_wait<1>(); else cp_wait<0>();
        __syncthreads();
        if (it + 2 < nk) load_chunk(it + 2);

        const uint32_t sA = sbase + (uint32_t)(it % 3) * GSTG;
        const uint32_t sB = sA + GB_HI;
        #pragma unroll
        for (int kc = 0; kc < 4; kc++) {
            const int c16 = kc * 2 + (grp >> 1);

            uint32_t ah[2][4];
            #pragma unroll
            for (int am = 0; am < 2; am++)
                ldm_x4(ah[am], sA + baseA[am] + ((uint32_t)(c16 ^ swA[am]) << 4));
            #pragma unroll
            for (int bt = 0; bt < 4; bt++) {
                uint32_t bh[4];
                ldm_x4(bh, sB + baseB[bt] + ((uint32_t)(c16 ^ swB[bt]) << 4));
                #pragma unroll
                for (int am = 0; am < 2; am++) {
                    mma_f16(acc[am][2 * bt],     ah[am], bh[0], bh[2]);
                    mma_f16(acc[am][2 * bt + 1], ah[am], bh[1], bh[3]);
                }
            }
        }
    }

    if (mode == 0) {
        #pragma unroll
        for (int am = 0; am < 2; am++) {
            int row = m0 + wm * 32 + am * 16 + (lane >> 2);
            #pragma unroll
            for (int bn = 0; bn < 8; bn++) {
                int col = n0 + wn * 64 + bn * 8 + (lane & 3) * 2;
                *(float2*)&C[(size_t)row * ldc + col]       = make_float2(acc[am][bn][0], acc[am][bn][1]);
                *(float2*)&C[(size_t)(row + 8) * ldc + col] = make_float2(acc[am][bn][2], acc[am][bn][3]);
            }
        }
    } else {
        #pragma unroll
        for (int am = 0; am < 2; am++) {
            int row = m0 + wm * 32 + am * 16 + (lane >> 2);
            #pragma unroll
            for (int bn = 0; bn < 8; bn++) {
                int col = n0 + wn * 64 + bn * 8 + (lane & 3) * 2;
                int i = (col & (HD - 1)) >> 1;
                bool rope = col < V_OFF;
                #pragma unroll
                for (int half = 0; half < 2; half++) {
                    int r = row + half * 8;
                    float v0 = acc[am][bn][2 * half], v1 = acc[am][bn][2 * half + 1];
                    if (rope) {
                        float c = cs[r * 64 + i], si = sn[r * 64 + i];
                        float t0 = v0 * c - v1 * si;
                        float t1 = v0 * si + v1 * c;
                        v0 = t0; v1 = t1;
                    }
                    uint32_t hb, lb;
                    pack_hl_f16(v0, v1, hb, lb);
                    *(uint32_t*)&Oh[(size_t)r * ldc + col] = hb;
                    *(uint32_t*)&Ol[(size_t)r * ldc + col] = lb;
                }
            }
        }
    }
}

// ---------------- tensor-core flash attention (fp16, causal, GQA 4:1) ----------------
// CTA: 128 threads (4 warps), q-tile 64, 2 CTAs/SM, single-sync pipeline.
#define ATT_SMEM (96 * 1024)

__global__ __launch_bounds__(128, 2) void attn_mma(
    const __half* __restrict__ qh_g, const __half* __restrict__ ql_g,
    __half* __restrict__ ah_g, int qbase)
{
    extern __shared__ __align__(1024) char smb[];
    const uint32_t sb = smem_u32(smb);
    const uint32_t sQh = sb, sQl = sb + 16 * 1024;

    const int tid = threadIdx.x, lane = tid & 31, wid = tid >> 5;
    const int qt = qbase + (int)gridDim.x - 1 - (int)blockIdx.x;
    const int h = blockIdx.y, kvh = h >> 2;
    const int q0 = qt * 64;
    const int wq = wid * 16;

    const int kRow = tid >> 4;
    const int kc16 = tid & 15;
    const uint32_t soK = (uint32_t)(kRow * 256)
                       + ((uint32_t)(kc16 ^ (kRow & 7)) << 4);
    const __half* kP = qh_g + (size_t)kRow * QKV_N + kvh * HD + kc16 * 8 + K_OFF;
    const __half* vP = kP + (V_OFF - K_OFF);

    #pragma unroll
    for (int i = 0; i < 8; i++) {
        int ch = tid + i * 128;
        int row = ch >> 4, c16 = ch & 15;
        uint32_t so = (uint32_t)(row * 256) + (uint32_t)((c16 ^ (row & 7)) << 4);
        size_t g = (size_t)(q0 + row) * QKV_N + h * HD + c16 * 8;
        cp16(sQh + so, qh_g + g);
        cp16(sQl + so, ql_g + g);
    }
    cp_commit();

    const int ktmax = qt;
    auto load_kv = [&](int kt) {
        const uint32_t st = sb + 32 * 1024 + (uint32_t)(kt & 1) * 32 * 1024;
        const size_t koff = (size_t)kt * 64 * QKV_N;
        #pragma unroll
        for (int i = 0; i < 8; i++) {
            cp16(st + soK + (uint32_t)(i * 2048),             kP + koff + (size_t)i * 8 * QKV_N);
            cp16(st + 16 * 1024 + soK + (uint32_t)(i * 2048), vP + koff + (size_t)i * 8 * QKV_N);
        }
        cp_commit();
    };
    load_kv(0);

    float oacc[16][4];
    #pragma unroll
    for (int a = 0; a < 16; a++)
        #pragma unroll
        for (int q = 0; q < 4; q++) oacc[a][q] = 0.f;
    float m0 = -1e30f, m1 = -1e30f, l0 = 0.f, l1 = 0.f;
    const float kscale = 0.08838834764831845f * 1.44269504088896f;

    const int rin = lane & 7, grp = lane >> 3;
    const int arow = wq + rin + (grp & 1) * 8;
    const int r0 = lane >> 2;

    for (int kt = 0; kt <= ktmax; kt++) {
        cp_wait<0>();
        __syncthreads();
        if (kt < ktmax) load_kv(kt + 1);

        {
            const uint32_t st = sb + 32 * 1024 + (uint32_t)(kt & 1) * 32 * 1024;

            float sc[8][4];
            #pragma unroll
            for (int a = 0; a < 8; a++)
                #pragma unroll
                for (int q = 0; q < 4; q++) sc[a][q] = 0.f;

            #pragma unroll
            for (int k16 = 0; k16 < 8; k16++) {
                const int c16 = k16 * 2 + (grp >> 1);
                uint32_t aoff = (uint32_t)(arow * 256) + (uint32_t)((c16 ^ (arow & 7)) << 4);
                uint32_t aqh[4], aql[4];
                ldm_x4(aqh, sQh + aoff);
                ldm_x4(aql, sQl + aoff);
                #pragma unroll
                for (int bp = 0; bp < 2; bp++) {
                    uint32_t bh[2][4];
                    #pragma unroll
                    for (int t = 0; t < 2; t++) {
                        int brow = (bp * 2 + t) * 16 + rin + (grp & 1) * 8;
                        uint32_t boff = (uint32_t)(brow * 256) + (uint32_t)((c16 ^ (brow & 7)) << 4);
                        ldm_x4(bh[t], st + boff);
                    }
                    #pragma unroll
                    for (int t = 0; t < 2; t++) {
                        int b = bp * 2 + t;
                        mma_f16(sc[2 * b],     aqh, bh[t][0], bh[t][2]);
                        mma_f16(sc[2 * b + 1], aqh, bh[t][1], bh[t][3]);
                    }
                    #pragma unroll
                    for (int t = 0; t < 2; t++) {
                        int b = bp * 2 + t;
                        mma_f16(sc[2 * b],     aql, bh[t][0], bh[t][2]);
                        mma_f16(sc[2 * b + 1], aql, bh[t][1], bh[t][3]);
                    }
                }
            }

            if (kt * 64 + 63 > q0 + wq) {
                int qr0 = q0 + wq + r0, qr1 = qr0 + 8;
                int cb = kt * 64 + 2 * (lane & 3);
                #pragma unroll
                for (int a = 0; a < 8; a++) {
                    int c0 = cb + a * 8, c1 = c0 + 1;
                    if (c0 > qr0) sc[a][0] = -1e30f;
                    if (c1 > qr0) sc[a][1] = -1e30f;
                    if (c0 > qr1) sc[a][2] = -1e30f;
                    if (c1 > qr1) sc[a][3] = -1e30f;
                }
            }

            float mx0 = -1e30f, mx1 = -1e30f;
            #pragma unroll
            for (int a = 0; a < 8; a++) {
                mx0 = fmaxf(mx0, fmaxf(sc[a][0], sc[a][1]));
                mx1 = fmaxf(mx1, fmaxf(sc[a][2], sc[a][3]));
            }
            mx0 = fmaxf(mx0, __shfl_xor_sync(0xffffffffu, mx0, 1));
            mx0 = fmaxf(mx0, __shfl_xor_sync(0xffffffffu, mx0, 2));
            mx1 = fmaxf(mx1, __shfl_xor_sync(0xffffffffu, mx1, 1));
            mx1 = fmaxf(mx1, __shfl_xor_sync(0xffffffffu, mx1, 2));
            float nm0 = fmaxf(m0, mx0), nm1 = fmaxf(m1, mx1);
            float corr0 = exp2f((m0 - nm0) * kscale);
            float corr1 = exp2f((m1 - nm1) * kscale);
            float s0 = 0.f, s1 = 0.f;
            #pragma unroll
            for (int a = 0; a < 8; a++) {
                sc[a][0] = exp2f((sc[a][0] - nm0) * kscale);
                sc[a][1] = exp2f((sc[a][1] - nm0) * kscale);
                sc[a][2] = exp2f((sc[a][2] - nm1) * kscale);
                sc[a][3] = exp2f((sc[a][3] - nm1) * kscale);
                s0 += sc[a][0] + sc[a][1];
                s1 += sc[a][2] + sc[a][3];
            }
            s0 += __shfl_xor_sync(0xffffffffu, s0, 1);
            s0 += __shfl_xor_sync(0xffffffffu, s0, 2);
            s1 += __shfl_xor_sync(0xffffffffu, s1, 1);
            s1 += __shfl_xor_sync(0xffffffffu, s1, 2);
            l0 = l0 * corr0 + s0;
            l1 = l1 * corr1 + s1;
            m0 = nm0; m1 = nm1;
            #pragma unroll
            for (int a = 0; a < 16; a++) {
                oacc[a][0] *= corr0; oacc[a][1] *= corr0;
                oacc[a][2] *= corr1; oacc[a][3] *= corr1;
            }

            #pragma unroll
            for (int t = 0; t < 4; t++) {
                uint32_t ph[4];
                ph[0] = pack_f16(sc[2 * t][0],     sc[2 * t][1]);
                ph[1] = pack_f16(sc[2 * t][2],     sc[2 * t][3]);
                ph[2] = pack_f16(sc[2 * t + 1][0], sc[2 * t + 1][1]);
                ph[3] = pack_f16(sc[2 * t + 1][2], sc[2 * t + 1][3]);
                #pragma unroll
                for (int dp = 0; dp < 4; dp++) {
                    uint32_t vh[2][4];
                    #pragma unroll
                    for (int u = 0; u < 2; u++) {
                        int d = dp * 2 + u;
                        int vrow = t * 16 + (grp & 1) * 8 + rin;
                        int c16 = d * 2 + (grp >> 1);
                        uint32_t voff = (uint32_t)(vrow * 256) + (uint32_t)((c16 ^ (vrow & 7)) << 4);
                        ldm_x4t(vh[u], st + 16 * 1024 + voff);
                    }
                    #pragma unroll
                    for (int u = 0; u < 2; u++) {
                        int d = dp * 2 + u;
                        mma_f16(oacc[2 * d],     ph, vh[u][0], vh[u][1]);
                        mma_f16(oacc[2 * d + 1], ph, vh[u][2], vh[u][3]);
                    }
                }
            }
        }
    }

    float inv0 = 1.f / l0, inv1 = 1.f / l1;
    int gr0 = q0 + wq + r0, gr1 = gr0 + 8;
    #pragma unroll
    for (int a = 0; a < 16; a++) {
        int d0 = a * 8 + 2 * (lane & 3);
        *(uint32_t*)&ah_g[(size_t)gr0 * DIM + h * HD + d0] =
            pack_f16(oacc[a][0] * inv0, oacc[a][1] * inv0);
        *(uint32_t*)&ah_g[(size_t)gr1 * DIM + h * HD + d0] =
            pack_f16(oacc[a][2] * inv1, oacc[a][3] * inv1);
    }
}

// ---------------- launch: fork-join pipeline over row halves ----------------
extern "C" void kernel_launch(void* const* d_in, const int* in_sizes, int n_in,
                              void* d_out, int out_size)
{
    const float* x  = (const float*)d_in[0];
    const float* fc = (const float*)d_in[1];
    const float* fs = (const float*)d_in[2];
    const float* wq = (const float*)d_in[5];
    const float* wk = (const float*)d_in[6];
    const float* wv = (const float*)d_in[7];
    const float* wo = (const float*)d_in[8];
    float* out = (float*)d_out;

    __half *qh, *ql, *xh, *wh, *oh, *ah;
    cudaGetSymbolAddress((void**)&qh, g_qh);  cudaGetSymbolAddress((void**)&ql, g_ql);
    cudaGetSymbolAddress((void**)&xh, g_xh);
    cudaGetSymbolAddress((void**)&wh, g_wh);  cudaGetSymbolAddress((void**)&oh, g_oh);
    cudaGetSymbolAddress((void**)&ah, g_ah);

    cudaFuncSetAttribute(gemm_f16, cudaFuncAttributeMaxDynamicSharedMemorySize, GEMM_SMEM);
    cudaFuncSetAttribute(attn_mma, cudaFuncAttributeMaxDynamicSharedMemorySize, ATT_SMEM);

    cudaStream_t s1;
    cudaStreamCreateWithFlags(&s1, cudaStreamNonBlocking);
    cudaEvent_t evQlo, evJoin;
    cudaEventCreateWithFlags(&evQlo, cudaEventDisableTiming);
    cudaEventCreateWithFlags(&evJoin, cudaEventDisableTiming);

    dim3 blk(256);
    split_all<<<(NTOT4 + 255) / 256, blk>>>(x, wq, wk, wv, wo, xh, wh, oh);

    // QKV rows 0-1023
    gemm_f16<<<dim3(8, QKV_N / 128), blk, GEMM_SMEM>>>(
        xh, wh, nullptr, QKV_N, 1, 0, fc, fs, qh, ql);
    cudaEventRecord(evQlo, 0);

    // QKV rows 1024-2047 (stream 0)  ||  attn q-tiles 0-15 (s1)
    gemm_f16<<<dim3(8, QKV_N / 128), blk, GEMM_SMEM>>>(
        xh, wh, nullptr, QKV_N, 1, 1024, fc, fs, qh, ql);
    cudaStreamWaitEvent(s1, evQlo, 0);
    attn_mma<<<dim3(16, NH), dim3(128), ATT_SMEM, s1>>>(qh, ql, ah, 0);

    // attn q-tiles 16-31 (stream 0, after QKV_hi)  ||  out-proj rows 0-1023 (s1)
    attn_mma<<<dim3(16, NH), dim3(128), ATT_SMEM>>>(qh, ql, ah, 16);
    gemm_f16<<<dim3(8, DIM / 128), blk, GEMM_SMEM, s1>>>(
        ah, oh, out, DIM, 0, 0, nullptr, nullptr, nullptr, nullptr);
    cudaEventRecord(evJoin, s1);

    // out-proj rows 1024-2047 (stream 0, after attn_hi), then join s1
    gemm_f16<<<dim3(8, DIM / 128), blk, GEMM_SMEM>>>(
        ah, oh, out, DIM, 0, 1024, nullptr, nullptr, nullptr, nullptr);
    cudaStreamWaitEvent(0, evJoin, 0);
}